// round 2
// baseline (speedup 1.0000x reference)
#include <cuda_runtime.h>
#include <cuda_bf16.h>
#include <math.h>

#define N_NODES 50000
#define D_IN    768
#define NHID    256
#define NCLASS  2

// ---------------- device scratch (no allocations allowed) ----------------
__device__ float g_C1[(size_t)N_NODES * 768];   // x @ [W1r1 | W1r2 | mlp1_W]; mlp block tanh'd in-place
__device__ float g_S1[(size_t)N_NODES * 512];   // spmm outputs (r1 cols 0..255, r2 cols 256..511)
__device__ float g_X1[(size_t)N_NODES * 256];   // fused layer-1 output
__device__ float g_Z2[(size_t)N_NODES * 6];     // x1 @ [W2r1 | W2r2 | mlp2_W]
__device__ float g_Wcat[768 * 768];             // packed layer-1 weights
__device__ float g_W2[256 * 6];                 // packed layer-2 weights

// ---------------- pack kernels ----------------
__global__ void pack_w1(const float* __restrict__ W1r1,
                        const float* __restrict__ W1r2,
                        const float* __restrict__ mlp1_W) {
    int idx = blockIdx.x * blockDim.x + threadIdx.x;
    if (idx >= 768 * 768) return;
    int k = idx / 768, c = idx % 768;
    float v;
    if (c < 256)       v = W1r1[k * 256 + c];
    else if (c < 512)  v = W1r2[k * 256 + (c - 256)];
    else               v = mlp1_W[k * 256 + (c - 512)];
    g_Wcat[idx] = v;
}

__global__ void pack_w2(const float* __restrict__ W2r1,
                        const float* __restrict__ W2r2,
                        const float* __restrict__ mlp2_W) {
    int idx = blockIdx.x * blockDim.x + threadIdx.x;
    if (idx >= 256 * 6) return;
    int k = idx / 6, j = idx % 6;
    float v;
    if (j < 2)      v = W2r1[k * 2 + j];
    else if (j < 4) v = W2r2[k * 2 + (j - 2)];
    else            v = mlp2_W[k * 2 + (j - 4)];
    g_W2[idx] = v;
}

// ---------------- zero S1 ----------------
__global__ void zero_s1() {
    size_t total4 = (size_t)N_NODES * 512 / 4;
    size_t i = (size_t)blockIdx.x * blockDim.x + threadIdx.x;
    size_t stride = (size_t)gridDim.x * blockDim.x;
    float4 z = make_float4(0.f, 0.f, 0.f, 0.f);
    float4* p = reinterpret_cast<float4*>(g_S1);
    for (; i < total4; i += stride) p[i] = z;
}

// ---------------- GEMM1: C1[M x 768] = x[M x 768] @ Wcat[768 x 768] ----------------
// 128x128x8 tile, 256 threads, 8x8 per thread. tanh(.+b) epilogue on cols >= 512.
#define BM 128
#define BN 128
#define BK 8
#define TM 8
#define TN 8

__global__ __launch_bounds__(256, 2)
void gemm1(const float* __restrict__ A,          // x, M x 768
           const float* __restrict__ mlp1_b,     // 256
           int M) {
    const int K = 768, NC = 768;
    __shared__ float As[BK][BM];
    __shared__ float Bs[BK][BN];

    const int cCol = blockIdx.x;   // 0..5
    const int cRow = blockIdx.y;   // 0..390
    const int tid = threadIdx.x;

    const int threadCol = tid % (BN / TN);   // 0..15
    const int threadRow = tid / (BN / TN);   // 0..15

    const int innerRowA = tid / 2;           // 0..127
    const int innerColA = tid % 2;           // *4 -> k offset
    const int innerRowB = tid / 32;          // 0..7
    const int innerColB = tid % 32;          // *4

    const int rowA = cRow * BM + innerRowA;

    float acc[TM][TN];
#pragma unroll
    for (int i = 0; i < TM; i++)
#pragma unroll
        for (int j = 0; j < TN; j++) acc[i][j] = 0.f;

    float regM[TM], regN[TN];

    const float* Bp = g_Wcat + cCol * BN;

    for (int k0 = 0; k0 < K; k0 += BK) {
        // load A tile (transposed into As[k][m]) with row guard
        float4 a = make_float4(0.f, 0.f, 0.f, 0.f);
        if (rowA < M)
            a = *reinterpret_cast<const float4*>(A + (size_t)rowA * K + k0 + innerColA * 4);
        As[innerColA * 4 + 0][innerRowA] = a.x;
        As[innerColA * 4 + 1][innerRowA] = a.y;
        As[innerColA * 4 + 2][innerRowA] = a.z;
        As[innerColA * 4 + 3][innerRowA] = a.w;

        // load B tile
        float4 b = *reinterpret_cast<const float4*>(Bp + (size_t)(k0 + innerRowB) * NC + innerColB * 4);
        *reinterpret_cast<float4*>(&Bs[innerRowB][innerColB * 4]) = b;

        __syncthreads();

#pragma unroll
        for (int kk = 0; kk < BK; kk++) {
#pragma unroll
            for (int i = 0; i < TM; i++) regM[i] = As[kk][threadRow * TM + i];
#pragma unroll
            for (int j = 0; j < TN; j++) regN[j] = Bs[kk][threadCol * TN + j];
#pragma unroll
            for (int i = 0; i < TM; i++)
#pragma unroll
                for (int j = 0; j < TN; j++) acc[i][j] = fmaf(regM[i], regN[j], acc[i][j]);
        }
        __syncthreads();
    }

    const int colBase = cCol * BN + threadCol * TN;
    const bool isMlp = (colBase >= 512);   // block cols 4,5 are fully the mlp branch

#pragma unroll
    for (int i = 0; i < TM; i++) {
        int row = cRow * BM + threadRow * TM + i;
        if (row >= M) continue;
        float* Crow = g_C1 + (size_t)row * 768 + colBase;
#pragma unroll
        for (int j = 0; j < TN; j++) {
            float v = acc[i][j];
            if (isMlp) v = tanhf(v + mlp1_b[colBase + j - 512]);
            Crow[j] = v;
        }
    }
}

// ---------------- SpMM 256-wide: one warp per edge ----------------
// IMPORTANT: g_C1/g_S1 are referenced from DEVICE code only (host-side symbol
// addresses are the host shadow and, with ATS on GB300, silently read host
// memory). Only integer offsets are passed from the host.
__global__ void spmm256(const int* __restrict__ rows,
                        const int* __restrict__ cols,
                        const float* __restrict__ vals,
                        int denseOff,      // column offset into g_C1 (stride 768)
                        int outOff,        // column offset into g_S1 (stride 512)
                        int E) {
    int w = (blockIdx.x * blockDim.x + threadIdx.x) >> 5;
    int lane = threadIdx.x & 31;
    if (w >= E) return;
    int r = __ldg(rows + w);
    int c = __ldg(cols + w);
    float v = __ldg(vals + w);
    const float* src = g_C1 + (size_t)c * 768 + denseOff;
    float* dst = g_S1 + (size_t)r * 512 + outOff;
#pragma unroll
    for (int p = 0; p < 2; p++) {
        int j = p * 128 + lane * 4;
        float4 s = *reinterpret_cast<const float4*>(src + j);
        s.x *= v; s.y *= v; s.z *= v; s.w *= v;
        asm volatile("red.global.add.v4.f32 [%0], {%1,%2,%3,%4};"
                     :: "l"(dst + j), "f"(s.x), "f"(s.y), "f"(s.z), "f"(s.w)
                     : "memory");
    }
}

// ---------------- attention fusion: one block (256 thr) per node ----------------
__global__ void fuse_att(const float* __restrict__ b1r1,
                         const float* __restrict__ b1r2,
                         const float* __restrict__ af) {   // af: [768,3] row-major
    int i = blockIdx.x;
    int h = threadIdx.x;
    int lane = h & 31, warp = h >> 5;

    float v1 = g_S1[(size_t)i * 512 + h] + b1r1[h];
    float v2 = g_S1[(size_t)i * 512 + 256 + h] + b1r2[h];
    float v3 = g_C1[(size_t)i * 768 + 512 + h];   // already tanh(.+b)

    float p0 = v1 * af[h * 3 + 0] + v2 * af[(256 + h) * 3 + 0] + v3 * af[(512 + h) * 3 + 0];
    float p1 = v1 * af[h * 3 + 1] + v2 * af[(256 + h) * 3 + 1] + v3 * af[(512 + h) * 3 + 1];
    float p2 = v1 * af[h * 3 + 2] + v2 * af[(256 + h) * 3 + 2] + v3 * af[(512 + h) * 3 + 2];

#pragma unroll
    for (int off = 16; off; off >>= 1) {
        p0 += __shfl_xor_sync(0xffffffffu, p0, off);
        p1 += __shfl_xor_sync(0xffffffffu, p1, off);
        p2 += __shfl_xor_sync(0xffffffffu, p2, off);
    }
    __shared__ float red[8][3];
    if (lane == 0) { red[warp][0] = p0; red[warp][1] = p1; red[warp][2] = p2; }
    __syncthreads();

    float a0 = 0.f, a1 = 0.f, a2 = 0.f;
#pragma unroll
    for (int w = 0; w < 8; w++) { a0 += red[w][0]; a1 += red[w][1]; a2 += red[w][2]; }

    a0 = fabsf(a0); a1 = fabsf(a1); a2 = fabsf(a2);
    float m = fmaxf(a0, fmaxf(a1, a2));
    float e0 = __expf(a0 - m), e1 = __expf(a1 - m), e2 = __expf(a2 - m);
    float inv = 1.0f / (e0 + e1 + e2);
    float w0 = e0 * inv, w1 = e1 * inv, w2 = e2 * inv;

    g_X1[(size_t)i * 256 + h] = v1 * w0 + v2 * w1 + v3 * w2;
}

// ---------------- GEMM2: Z2[N x 6] = X1[N x 256] @ W2[256 x 6]; one warp per row ----------------
__global__ void gemm2(int M) {
    __shared__ float Ws[256 * 6];
    for (int t = threadIdx.x; t < 256 * 6; t += blockDim.x) Ws[t] = g_W2[t];
    __syncthreads();

    int warp = threadIdx.x >> 5, lane = threadIdx.x & 31;
    int row = blockIdx.x * 8 + warp;
    if (row >= M) return;

    float acc[6] = {0.f, 0.f, 0.f, 0.f, 0.f, 0.f};
    const float* xr = g_X1 + (size_t)row * 256;
    for (int k = lane; k < 256; k += 32) {
        float xv = xr[k];
#pragma unroll
        for (int j = 0; j < 6; j++) acc[j] = fmaf(xv, Ws[k * 6 + j], acc[j]);
    }
#pragma unroll
    for (int off = 16; off; off >>= 1)
#pragma unroll
        for (int j = 0; j < 6; j++) acc[j] += __shfl_xor_sync(0xffffffffu, acc[j], off);

    if (lane == 0) {
        float* z = g_Z2 + (size_t)row * 6;
#pragma unroll
        for (int j = 0; j < 6; j++) z[j] = acc[j];
    }
}

// ---------------- out init: out = b2r1 + b2r2 + tanh(z_mlp + mlp2_b) ----------------
__global__ void out_init(const float* __restrict__ b2r1,
                         const float* __restrict__ b2r2,
                         const float* __restrict__ mlp2_b,
                         float* __restrict__ out, int M) {
    int i = blockIdx.x * blockDim.x + threadIdx.x;
    if (i >= M) return;
    const float* z = g_Z2 + (size_t)i * 6;
    out[i * 2 + 0] = b2r1[0] + b2r2[0] + tanhf(z[4] + mlp2_b[0]);
    out[i * 2 + 1] = b2r1[1] + b2r2[1] + tanhf(z[5] + mlp2_b[1]);
}

// ---------------- SpMM 2-wide: one thread per edge (reads g_Z2 device-side) ----------------
__global__ void spmm2(const int* __restrict__ rows,
                      const int* __restrict__ cols,
                      const float* __restrict__ vals,
                      int zOff, float* __restrict__ out, int E) {
    int i = blockIdx.x * blockDim.x + threadIdx.x;
    if (i >= E) return;
    int r = __ldg(rows + i);
    int c = __ldg(cols + i);
    float v = __ldg(vals + i);
    float2 s = *reinterpret_cast<const float2*>(g_Z2 + (size_t)c * 6 + zOff);
    s.x *= v; s.y *= v;
    asm volatile("red.global.add.v2.f32 [%0], {%1,%2};"
                 :: "l"(out + (size_t)r * 2), "f"(s.x), "f"(s.y)
                 : "memory");
}

// ---------------- launch ----------------
extern "C" void kernel_launch(void* const* d_in, const int* in_sizes, int n_in,
                              void* d_out, int out_size) {
    const float* x        = (const float*)d_in[0];
    const int*   adj_rows = (const int*)d_in[1];
    const int*   adj_cols = (const int*)d_in[2];
    const float* adj_vals = (const float*)d_in[3];
    const int*   s_rows   = (const int*)d_in[4];
    const int*   s_cols   = (const int*)d_in[5];
    const float* s_vals   = (const float*)d_in[6];
    const float* W1r1     = (const float*)d_in[7];
    const float* b1r1     = (const float*)d_in[8];
    const float* W1r2     = (const float*)d_in[9];
    const float* b1r2     = (const float*)d_in[10];
    const float* mlp1_W   = (const float*)d_in[11];
    const float* mlp1_b   = (const float*)d_in[12];
    const float* af1_w    = (const float*)d_in[13];
    const float* W2r1     = (const float*)d_in[14];
    const float* b2r1     = (const float*)d_in[15];
    const float* W2r2     = (const float*)d_in[16];
    const float* b2r2     = (const float*)d_in[17];
    const float* mlp2_W   = (const float*)d_in[18];
    const float* mlp2_b   = (const float*)d_in[19];
    float* out = (float*)d_out;

    const int E = in_sizes[1];
    const int M = N_NODES;

    // pack weights + zero accumulators
    pack_w1<<<(768 * 768 + 255) / 256, 256>>>(W1r1, W1r2, mlp1_W);
    pack_w2<<<(256 * 6 + 255) / 256, 256>>>(W2r1, W2r2, mlp2_W);
    zero_s1<<<1184, 256>>>();

    // layer 1 big GEMM (with tanh epilogue on mlp block)
    dim3 g1(768 / BN, (M + BM - 1) / BM);
    gemm1<<<g1, 256>>>(x, mlp1_b, M);

    // layer 1 spmms (device globals referenced inside the kernel; offsets only)
    int spmmBlocks = (E * 32 + 255) / 256;
    spmm256<<<spmmBlocks, 256>>>(adj_rows, adj_cols, adj_vals, 0,   0,   E);
    spmm256<<<spmmBlocks, 256>>>(s_rows,   s_cols,   s_vals,   256, 256, E);

    // attention fusion
    fuse_att<<<M, 256>>>(b1r1, b1r2, af1_w);

    // layer 2
    gemm2<<<(M + 7) / 8, 256>>>(M);
    out_init<<<(M + 255) / 256, 256>>>(b2r1, b2r2, mlp2_b, out, M);
    spmm2<<<(E + 255) / 256, 256>>>(adj_rows, adj_cols, adj_vals, 0, out, E);
    spmm2<<<(E + 255) / 256, 256>>>(s_rows,   s_cols,   s_vals,   2, out, E);
}

// round 4
// speedup vs baseline: 1.5474x; 1.5474x over previous
#include <cuda_runtime.h>
#include <cuda_bf16.h>
#include <math.h>
#include <stdint.h>

#define N_NODES 50000
#define D_IN    768
#define NHID    256

// ---------------- device scratch (no allocations allowed) ----------------
__device__ float g_C1[(size_t)N_NODES * 768];   // x @ [W1r1 | W1r2 | mlp1_W]; mlp block tanh'd
__device__ float g_S1[(size_t)N_NODES * 512];   // spmm outputs (r1 cols 0..255, r2 cols 256..511)
__device__ float g_X1[(size_t)N_NODES * 256];   // fused layer-1 output
__device__ float g_Z2[(size_t)N_NODES * 6];     // x1 @ [W2r1 | W2r2 | mlp2_W]
__device__ float g_W2[256 * 6];                 // packed layer-2 weights

// bf16 split operands for the tensor-core GEMM
__device__ __nv_bfloat16 g_xhi[(size_t)N_NODES * 768];
__device__ __nv_bfloat16 g_xlo[(size_t)N_NODES * 768];
__device__ __nv_bfloat16 g_Whi[768 * 768];      // transposed: [n][k] = Wcat[k][n]
__device__ __nv_bfloat16 g_Wlo[768 * 768];

// ================= helpers =================
__device__ __forceinline__ uint32_t smem_u32(const void* p) {
    uint32_t a;
    asm("{ .reg .u64 t; cvta.to.shared.u64 t, %1; cvt.u32.u64 %0, t; }" : "=r"(a) : "l"(p));
    return a;
}
__device__ __forceinline__ void cp16(uint32_t dst, const void* src) {
    asm volatile("cp.async.cg.shared.global [%0], [%1], 16;" :: "r"(dst), "l"(src));
}
__device__ __forceinline__ void ldsm_x4(uint32_t* r, uint32_t addr) {
    asm volatile("ldmatrix.sync.aligned.m8n8.x4.shared.b16 {%0,%1,%2,%3}, [%4];"
                 : "=r"(r[0]), "=r"(r[1]), "=r"(r[2]), "=r"(r[3]) : "r"(addr));
}
__device__ __forceinline__ void mma_bf16(float* c, const uint32_t* a, const uint32_t* b) {
    asm volatile("mma.sync.aligned.m16n8k16.row.col.f32.bf16.bf16.f32 "
                 "{%0,%1,%2,%3}, {%4,%5,%6,%7}, {%8,%9}, {%0,%1,%2,%3};"
                 : "+f"(c[0]), "+f"(c[1]), "+f"(c[2]), "+f"(c[3])
                 : "r"(a[0]), "r"(a[1]), "r"(a[2]), "r"(a[3]), "r"(b[0]), "r"(b[1]));
}

// ---------------- prep: split x into bf16 hi/lo ----------------
__global__ void split_x(const float* __restrict__ x) {
    size_t i = (size_t)blockIdx.x * blockDim.x + threadIdx.x;
    size_t total = (size_t)N_NODES * 768;
    size_t stride = (size_t)gridDim.x * blockDim.x;
    for (; i < total; i += stride) {
        float v = x[i];
        __nv_bfloat16 hi = __float2bfloat16(v);
        g_xhi[i] = hi;
        g_xlo[i] = __float2bfloat16(v - __bfloat162float(hi));
    }
}

// ---------------- prep: pack + transpose + split layer-1 weights ----------------
__global__ void pack_w1split(const float* __restrict__ W1r1,
                             const float* __restrict__ W1r2,
                             const float* __restrict__ mlp1_W) {
    int idx = blockIdx.x * blockDim.x + threadIdx.x;
    if (idx >= 768 * 768) return;
    int n = idx / 768, k = idx % 768;     // output [n][k] = W[k][n]
    float v;
    if (n < 256)       v = W1r1[k * 256 + n];
    else if (n < 512)  v = W1r2[k * 256 + (n - 256)];
    else               v = mlp1_W[k * 256 + (n - 512)];
    __nv_bfloat16 hi = __float2bfloat16(v);
    g_Whi[idx] = hi;
    g_Wlo[idx] = __float2bfloat16(v - __bfloat162float(hi));
}

__global__ void pack_w2(const float* __restrict__ W2r1,
                        const float* __restrict__ W2r2,
                        const float* __restrict__ mlp2_W) {
    int idx = blockIdx.x * blockDim.x + threadIdx.x;
    if (idx >= 256 * 6) return;
    int k = idx / 6, j = idx % 6;
    float v;
    if (j < 2)      v = W2r1[k * 2 + j];
    else if (j < 4) v = W2r2[k * 2 + (j - 2)];
    else            v = mlp2_W[k * 2 + (j - 4)];
    g_W2[idx] = v;
}

__global__ void zero_s1() {
    size_t total4 = (size_t)N_NODES * 512 / 4;
    size_t i = (size_t)blockIdx.x * blockDim.x + threadIdx.x;
    size_t stride = (size_t)gridDim.x * blockDim.x;
    float4 z = make_float4(0.f, 0.f, 0.f, 0.f);
    float4* p = reinterpret_cast<float4*>(g_S1);
    for (; i < total4; i += stride) p[i] = z;
}

// ================= GEMM1 via mma.sync (HMMA, bf16 split) =================
// C1[M x 768] = x @ Wcat. hi*hi + hi*lo + lo*hi, fp32 accum.
// CTA 128x128, 8 warps (2x4 grid, 64x32 warp tiles), BK=16, double-buffered cp.async.
#define BKC 16
#define ROWB 48                         // padded row stride in bytes (24 bf16)
#define GTILE (128 * ROWB)              // 6144 B per operand tile
#define GSTAGE (4 * GTILE)              // Ahi, Alo, Bhi, Blo = 24576 B
#define GSMEM  (2 * GSTAGE)             // 49152 B = default dynamic smem limit
#define NCHUNK (768 / BKC)              // 48

__global__ __launch_bounds__(256)
void gemm1_mma(const float* __restrict__ mlp1_b, int M) {
    extern __shared__ char dsm[];
    const uint32_t base = smem_u32(dsm);

    const int tid = threadIdx.x;
    const int lane = tid & 31, wid = tid >> 5;
    const int warp_m = wid >> 2;          // 0..1
    const int warp_n = wid & 3;           // 0..3
    const int tileM = blockIdx.y * 128;
    const int nBase = blockIdx.x * 128;

    // cp.async per-thread assignment: one 16B chunk per operand tile
    const int ldR = tid >> 1;             // row 0..127
    const int ldG = tid & 1;              // 16B group within 32B row
    int srcRowA = tileM + ldR; if (srcRowA >= M) srcRowA = M - 1;
    const uint32_t ldDst = ldR * ROWB + ldG * 16;
    const size_t aBase = (size_t)srcRowA * 768 + ldG * 8;
    const size_t bBase = (size_t)(nBase + ldR) * 768 + ldG * 8;

    // ldmatrix per-thread source offsets
    // A tile mi: rows warp_m*64 + mi*16 + (lane%16), k-quad (lane/16)*8
    const int aRow = warp_m * 64 + (lane & 15);
    const int aK   = (lane >> 4) * 8;
    uint32_t aOff[4];
#pragma unroll
    for (int mi = 0; mi < 4; mi++) aOff[mi] = (uint32_t)((aRow + mi * 16) * ROWB + aK * 2);
    // B pair p (two n8 tiles): n = warp_n*32 + p*16 + (lane%8) + (lane/16)*8, k = ((lane>>3)&1)*8
    const int bN = warp_n * 32 + (lane & 7) + ((lane >> 4) << 3);
    const int bK = ((lane >> 3) & 1) * 8;
    uint32_t bOff[2];
#pragma unroll
    for (int p = 0; p < 2; p++) bOff[p] = (uint32_t)((bN + p * 16) * ROWB + bK * 2);

    float acc[4][4][4];
#pragma unroll
    for (int mi = 0; mi < 4; mi++)
#pragma unroll
        for (int ni = 0; ni < 4; ni++)
#pragma unroll
            for (int r = 0; r < 4; r++) acc[mi][ni][r] = 0.f;

    // prologue: chunk 0 -> stage 0
    {
        uint32_t st = base;
        cp16(st + ldDst,             g_xhi + aBase);
        cp16(st + GTILE + ldDst,     g_xlo + aBase);
        cp16(st + 2 * GTILE + ldDst, g_Whi + bBase);
        cp16(st + 3 * GTILE + ldDst, g_Wlo + bBase);
        asm volatile("cp.async.commit_group;" ::: "memory");
    }

    for (int kc = 0; kc < NCHUNK; ++kc) {
        const int cur = kc & 1;
        if (kc + 1 < NCHUNK) {
            const int k0 = (kc + 1) * BKC;
            uint32_t st = base + (1 - cur) * GSTAGE;
            cp16(st + ldDst,             g_xhi + aBase + k0);
            cp16(st + GTILE + ldDst,     g_xlo + aBase + k0);
            cp16(st + 2 * GTILE + ldDst, g_Whi + bBase + k0);
            cp16(st + 3 * GTILE + ldDst, g_Wlo + bBase + k0);
            asm volatile("cp.async.commit_group;" ::: "memory");
            asm volatile("cp.async.wait_group 1;" ::: "memory");
        } else {
            asm volatile("cp.async.wait_group 0;" ::: "memory");
        }
        __syncthreads();

        const uint32_t st = base + cur * GSTAGE;
        uint32_t bh[2][4], bl[2][4];
#pragma unroll
        for (int p = 0; p < 2; p++) {
            ldsm_x4(bh[p], st + 2 * GTILE + bOff[p]);
            ldsm_x4(bl[p], st + 3 * GTILE + bOff[p]);
        }
#pragma unroll
        for (int mi = 0; mi < 4; mi++) {
            uint32_t ah[4], al[4];
            ldsm_x4(ah, st + aOff[mi]);
            ldsm_x4(al, st + GTILE + aOff[mi]);
#pragma unroll
            for (int ni = 0; ni < 4; ni++) {
                const int p = ni >> 1, h = (ni & 1) * 2;
                mma_bf16(acc[mi][ni], ah, &bh[p][h]);
                mma_bf16(acc[mi][ni], ah, &bl[p][h]);
                mma_bf16(acc[mi][ni], al, &bh[p][h]);
            }
        }
        __syncthreads();   // protect buffer(1-cur) before next iteration's cp.async
    }

    // epilogue
    const bool isMlp = (nBase >= 512);
    const int rBase = tileM + warp_m * 64 + (lane >> 2);
    const int cBase = nBase + warp_n * 32 + 2 * (lane & 3);
#pragma unroll
    for (int mi = 0; mi < 4; mi++) {
#pragma unroll
        for (int half = 0; half < 2; half++) {
            const int row = rBase + mi * 16 + half * 8;
            if (row >= M) continue;
            float* dst = g_C1 + (size_t)row * 768;
#pragma unroll
            for (int ni = 0; ni < 4; ni++) {
                const int col = cBase + ni * 8;
                float v0 = acc[mi][ni][half * 2 + 0];
                float v1 = acc[mi][ni][half * 2 + 1];
                if (isMlp) {
                    v0 = tanhf(v0 + mlp1_b[col - 512]);
                    v1 = tanhf(v1 + mlp1_b[col - 511]);
                }
                *reinterpret_cast<float2*>(dst + col) = make_float2(v0, v1);
            }
        }
    }
}

// ---------------- SpMM 256-wide: one warp per edge ----------------
__global__ void spmm256(const int* __restrict__ rows,
                        const int* __restrict__ cols,
                        const float* __restrict__ vals,
                        int denseOff, int outOff, int E) {
    int w = (blockIdx.x * blockDim.x + threadIdx.x) >> 5;
    int lane = threadIdx.x & 31;
    if (w >= E) return;
    int r = __ldg(rows + w);
    int c = __ldg(cols + w);
    float v = __ldg(vals + w);
    const float* src = g_C1 + (size_t)c * 768 + denseOff;
    float* dst = g_S1 + (size_t)r * 512 + outOff;
#pragma unroll
    for (int p = 0; p < 2; p++) {
        int j = p * 128 + lane * 4;
        float4 s = *reinterpret_cast<const float4*>(src + j);
        s.x *= v; s.y *= v; s.z *= v; s.w *= v;
        asm volatile("red.global.add.v4.f32 [%0], {%1,%2,%3,%4};"
                     :: "l"(dst + j), "f"(s.x), "f"(s.y), "f"(s.z), "f"(s.w)
                     : "memory");
    }
}

// ---------------- attention fusion: one block (256 thr) per node ----------------
__global__ void fuse_att(const float* __restrict__ b1r1,
                         const float* __restrict__ b1r2,
                         const float* __restrict__ af) {
    int i = blockIdx.x;
    int h = threadIdx.x;
    int lane = h & 31, warp = h >> 5;

    float v1 = g_S1[(size_t)i * 512 + h] + b1r1[h];
    float v2 = g_S1[(size_t)i * 512 + 256 + h] + b1r2[h];
    float v3 = g_C1[(size_t)i * 768 + 512 + h];

    float p0 = v1 * af[h * 3 + 0] + v2 * af[(256 + h) * 3 + 0] + v3 * af[(512 + h) * 3 + 0];
    float p1 = v1 * af[h * 3 + 1] + v2 * af[(256 + h) * 3 + 1] + v3 * af[(512 + h) * 3 + 1];
    float p2 = v1 * af[h * 3 + 2] + v2 * af[(256 + h) * 3 + 2] + v3 * af[(512 + h) * 3 + 2];

#pragma unroll
    for (int off = 16; off; off >>= 1) {
        p0 += __shfl_xor_sync(0xffffffffu, p0, off);
        p1 += __shfl_xor_sync(0xffffffffu, p1, off);
        p2 += __shfl_xor_sync(0xffffffffu, p2, off);
    }
    __shared__ float red[8][3];
    if (lane == 0) { red[warp][0] = p0; red[warp][1] = p1; red[warp][2] = p2; }
    __syncthreads();

    float a0 = 0.f, a1 = 0.f, a2 = 0.f;
#pragma unroll
    for (int w = 0; w < 8; w++) { a0 += red[w][0]; a1 += red[w][1]; a2 += red[w][2]; }

    a0 = fabsf(a0); a1 = fabsf(a1); a2 = fabsf(a2);
    float m = fmaxf(a0, fmaxf(a1, a2));
    float e0 = __expf(a0 - m), e1 = __expf(a1 - m), e2 = __expf(a2 - m);
    float inv = 1.0f / (e0 + e1 + e2);

    g_X1[(size_t)i * 256 + h] = v1 * (e0 * inv) + v2 * (e1 * inv) + v3 * (e2 * inv);
}

// ---------------- GEMM2 ----------------
__global__ void gemm2(int M) {
    __shared__ float Ws[256 * 6];
    for (int t = threadIdx.x; t < 256 * 6; t += blockDim.x) Ws[t] = g_W2[t];
    __syncthreads();

    int warp = threadIdx.x >> 5, lane = threadIdx.x & 31;
    int row = blockIdx.x * 8 + warp;
    if (row >= M) return;

    float acc[6] = {0.f, 0.f, 0.f, 0.f, 0.f, 0.f};
    const float* xr = g_X1 + (size_t)row * 256;
    for (int k = lane; k < 256; k += 32) {
        float xv = xr[k];
#pragma unroll
        for (int j = 0; j < 6; j++) acc[j] = fmaf(xv, Ws[k * 6 + j], acc[j]);
    }
#pragma unroll
    for (int off = 16; off; off >>= 1)
#pragma unroll
        for (int j = 0; j < 6; j++) acc[j] += __shfl_xor_sync(0xffffffffu, acc[j], off);

    if (lane == 0) {
        float* z = g_Z2 + (size_t)row * 6;
#pragma unroll
        for (int j = 0; j < 6; j++) z[j] = acc[j];
    }
}

__global__ void out_init(const float* __restrict__ b2r1,
                         const float* __restrict__ b2r2,
                         const float* __restrict__ mlp2_b,
                         float* __restrict__ out, int M) {
    int i = blockIdx.x * blockDim.x + threadIdx.x;
    if (i >= M) return;
    const float* z = g_Z2 + (size_t)i * 6;
    out[i * 2 + 0] = b2r1[0] + b2r2[0] + tanhf(z[4] + mlp2_b[0]);
    out[i * 2 + 1] = b2r1[1] + b2r2[1] + tanhf(z[5] + mlp2_b[1]);
}

__global__ void spmm2(const int* __restrict__ rows,
                      const int* __restrict__ cols,
                      const float* __restrict__ vals,
                      int zOff, float* __restrict__ out, int E) {
    int i = blockIdx.x * blockDim.x + threadIdx.x;
    if (i >= E) return;
    int r = __ldg(rows + i);
    int c = __ldg(cols + i);
    float v = __ldg(vals + i);
    float2 s = *reinterpret_cast<const float2*>(g_Z2 + (size_t)c * 6 + zOff);
    s.x *= v; s.y *= v;
    asm volatile("red.global.add.v2.f32 [%0], {%1,%2};"
                 :: "l"(out + (size_t)r * 2), "f"(s.x), "f"(s.y)
                 : "memory");
}

// ---------------- launch ----------------
extern "C" void kernel_launch(void* const* d_in, const int* in_sizes, int n_in,
                              void* d_out, int out_size) {
    const float* x        = (const float*)d_in[0];
    const int*   adj_rows = (const int*)d_in[1];
    const int*   adj_cols = (const int*)d_in[2];
    const float* adj_vals = (const float*)d_in[3];
    const int*   s_rows   = (const int*)d_in[4];
    const int*   s_cols   = (const int*)d_in[5];
    const float* s_vals   = (const float*)d_in[6];
    const float* W1r1     = (const float*)d_in[7];
    const float* b1r1     = (const float*)d_in[8];
    const float* W1r2     = (const float*)d_in[9];
    const float* b1r2     = (const float*)d_in[10];
    const float* mlp1_W   = (const float*)d_in[11];
    const float* mlp1_b   = (const float*)d_in[12];
    const float* af1_w    = (const float*)d_in[13];
    const float* W2r1     = (const float*)d_in[14];
    const float* b2r1     = (const float*)d_in[15];
    const float* W2r2     = (const float*)d_in[16];
    const float* b2r2     = (const float*)d_in[17];
    const float* mlp2_W   = (const float*)d_in[18];
    const float* mlp2_b   = (const float*)d_in[19];
    float* out = (float*)d_out;

    const int E = in_sizes[1];
    const int M = N_NODES;

    // prep
    split_x<<<1184, 256>>>(x);
    pack_w1split<<<(768 * 768 + 255) / 256, 256>>>(W1r1, W1r2, mlp1_W);
    pack_w2<<<(256 * 6 + 255) / 256, 256>>>(W2r1, W2r2, mlp2_W);
    zero_s1<<<1184, 256>>>();

    // layer 1 big GEMM on tensor cores (HMMA)
    dim3 g1(6, (M + 127) / 128);
    gemm1_mma<<<g1, 256, GSMEM>>>(mlp1_b, M);

    // layer 1 spmms
    int spmmBlocks = (E * 32 + 255) / 256;
    spmm256<<<spmmBlocks, 256>>>(adj_rows, adj_cols, adj_vals, 0,   0,   E);
    spmm256<<<spmmBlocks, 256>>>(s_rows,   s_cols,   s_vals,   256, 256, E);

    // attention fusion
    fuse_att<<<M, 256>>>(b1r1, b1r2, af1_w);

    // layer 2
    gemm2<<<(M + 7) / 8, 256>>>(M);
    out_init<<<(M + 255) / 256, 256>>>(b2r1, b2r2, mlp2_b, out, M);
    spmm2<<<(E + 255) / 256, 256>>>(adj_rows, adj_cols, adj_vals, 0, out, E);
    spmm2<<<(E + 255) / 256, 256>>>(s_rows,   s_cols,   s_vals,   2, out, E);
}

// round 6
// speedup vs baseline: 1.6316x; 1.0544x over previous
#include <cuda_runtime.h>
#include <cuda_bf16.h>
#include <math.h>
#include <stdint.h>

#define N_NODES 50000
#define D_IN    768
#define NHID    256

// ---------------- device scratch (no allocations allowed) ----------------
__device__ float g_C1[(size_t)N_NODES * 768];   // x @ [W1r1 | W1r2 | mlp1_W]; mlp block tanh'd
__device__ float g_S1[(size_t)N_NODES * 512];   // spmm outputs (r1 cols 0..255, r2 cols 256..511)
__device__ float g_X1[(size_t)N_NODES * 256];   // fused layer-1 output
__device__ float g_Z2[(size_t)N_NODES * 4];     // x1 @ [W2r1 | W2r2] (r1 cols 0..1, r2 cols 2..3)

// bf16 split operands for the tensor-core GEMM
__device__ __nv_bfloat16 g_xhi[(size_t)N_NODES * 768];
__device__ __nv_bfloat16 g_xlo[(size_t)N_NODES * 768];
__device__ __nv_bfloat16 g_Whi[768 * 768];      // transposed: [n][k] = Wcat[k][n]
__device__ __nv_bfloat16 g_Wlo[768 * 768];

// ================= helpers =================
__device__ __forceinline__ uint32_t smem_u32(const void* p) {
    uint32_t a;
    asm("{ .reg .u64 t; cvta.to.shared.u64 t, %1; cvt.u32.u64 %0, t; }" : "=r"(a) : "l"(p));
    return a;
}
__device__ __forceinline__ void cp16(uint32_t dst, const void* src) {
    asm volatile("cp.async.cg.shared.global [%0], [%1], 16;" :: "r"(dst), "l"(src));
}
__device__ __forceinline__ void ldsm_x4(uint32_t* r, uint32_t addr) {
    asm volatile("ldmatrix.sync.aligned.m8n8.x4.shared.b16 {%0,%1,%2,%3}, [%4];"
                 : "=r"(r[0]), "=r"(r[1]), "=r"(r[2]), "=r"(r[3]) : "r"(addr));
}
__device__ __forceinline__ void mma_bf16(float* c, const uint32_t* a, const uint32_t* b) {
    asm volatile("mma.sync.aligned.m16n8k16.row.col.f32.bf16.bf16.f32 "
                 "{%0,%1,%2,%3}, {%4,%5,%6,%7}, {%8,%9}, {%0,%1,%2,%3};"
                 : "+f"(c[0]), "+f"(c[1]), "+f"(c[2]), "+f"(c[3])
                 : "r"(a[0]), "r"(a[1]), "r"(a[2]), "r"(a[3]), "r"(b[0]), "r"(b[1]));
}

// ---------------- prep: split x into bf16 hi/lo AND zero g_S1 ----------------
__global__ void split_x_zero(const float* __restrict__ x) {
    size_t stride = (size_t)gridDim.x * blockDim.x;
    size_t i = (size_t)blockIdx.x * blockDim.x + threadIdx.x;
    const size_t totalX = (size_t)N_NODES * 768;
    for (size_t j = i; j < totalX; j += stride) {
        float v = x[j];
        __nv_bfloat16 hi = __float2bfloat16(v);
        g_xhi[j] = hi;
        g_xlo[j] = __float2bfloat16(v - __bfloat162float(hi));
    }
    const size_t totalS4 = (size_t)N_NODES * 512 / 4;
    float4 z = make_float4(0.f, 0.f, 0.f, 0.f);
    float4* p = reinterpret_cast<float4*>(g_S1);
    for (size_t j = i; j < totalS4; j += stride) p[j] = z;
}

// ---------------- prep: pack + transpose + split layer-1 weights ----------------
__global__ void pack_w1split(const float* __restrict__ W1r1,
                             const float* __restrict__ W1r2,
                             const float* __restrict__ mlp1_W) {
    int idx = blockIdx.x * blockDim.x + threadIdx.x;
    if (idx >= 768 * 768) return;
    int n = idx / 768, k = idx % 768;     // output [n][k] = W[k][n]
    float v;
    if (n < 256)       v = W1r1[k * 256 + n];
    else if (n < 512)  v = W1r2[k * 256 + (n - 256)];
    else               v = mlp1_W[k * 256 + (n - 512)];
    __nv_bfloat16 hi = __float2bfloat16(v);
    g_Whi[idx] = hi;
    g_Wlo[idx] = __float2bfloat16(v - __bfloat162float(hi));
}

// ================= GEMM1 via mma.sync (HMMA, bf16 split) =================
// C1[M x 768] = x @ Wcat. hi*hi + hi*lo + lo*hi, fp32 accum.
// CTA 128x128, 8 warps (2x4, 64x32 warp tiles), BK=16.
// 3-stage pipeline, chunk c -> stage c%3, prefetch distance 2, ONE barrier/iter.
#define BKC 16
#define ROWB 48                         // padded row stride in bytes (24 bf16)
#define GTILE (128 * ROWB)              // 6144 B per operand tile
#define GSTAGE (4 * GTILE)              // Ahi, Alo, Bhi, Blo = 24576 B
#define NSTAGE 3
#define GSMEM  (NSTAGE * GSTAGE)        // 73728 B (needs opt-in attribute)
#define NCHUNK (768 / BKC)              // 48

__global__ __launch_bounds__(256, 2)
void gemm1_mma(const float* __restrict__ mlp1_b, int M) {
    extern __shared__ char dsm[];
    const uint32_t base = smem_u32(dsm);

    const int tid = threadIdx.x;
    const int lane = tid & 31, wid = tid >> 5;
    const int warp_m = wid >> 2;          // 0..1
    const int warp_n = wid & 3;           // 0..3
    const int tileM = blockIdx.y * 128;
    const int nBase = blockIdx.x * 128;

    // cp.async per-thread assignment: one 16B chunk per operand tile
    const int ldR = tid >> 1;             // row 0..127
    const int ldG = tid & 1;              // which 16B half of the 32B row
    int srcRowA = tileM + ldR; if (srcRowA >= M) srcRowA = M - 1;
    const uint32_t ldDst = ldR * ROWB + ldG * 16;
    const size_t aBase = (size_t)srcRowA * 768 + ldG * 8;
    const size_t bBase = (size_t)(nBase + ldR) * 768 + ldG * 8;

    // ldmatrix per-thread source offsets
    const int aRow = warp_m * 64 + (lane & 15);
    const int aK   = (lane >> 4) * 8;
    uint32_t aOff[4];
#pragma unroll
    for (int mi = 0; mi < 4; mi++) aOff[mi] = (uint32_t)((aRow + mi * 16) * ROWB + aK * 2);
    const int bN = warp_n * 32 + (lane & 7) + ((lane >> 4) << 3);
    const int bK = ((lane >> 3) & 1) * 8;
    uint32_t bOff[2];
#pragma unroll
    for (int p = 0; p < 2; p++) bOff[p] = (uint32_t)((bN + p * 16) * ROWB + bK * 2);

    float acc[4][4][4];
#pragma unroll
    for (int mi = 0; mi < 4; mi++)
#pragma unroll
        for (int ni = 0; ni < 4; ni++)
#pragma unroll
            for (int r = 0; r < 4; r++) acc[mi][ni][r] = 0.f;

    // prologue: chunks 0,1 -> stages 0,1
#pragma unroll
    for (int pc = 0; pc < 2; pc++) {
        uint32_t st = base + pc * GSTAGE;
        const size_t k0 = (size_t)pc * BKC;
        cp16(st + ldDst,             g_xhi + aBase + k0);
        cp16(st + GTILE + ldDst,     g_xlo + aBase + k0);
        cp16(st + 2 * GTILE + ldDst, g_Whi + bBase + k0);
        cp16(st + 3 * GTILE + ldDst, g_Wlo + bBase + k0);
        asm volatile("cp.async.commit_group;" ::: "memory");
    }

    for (int kc = 0; kc < NCHUNK; ++kc) {
        // chunk kc must be resident. While kc+1 is still committed-in-flight,
        // allow 1 pending group; on the final iteration nothing newer exists,
        // so drain fully.
        if (kc + 1 < NCHUNK) {
            asm volatile("cp.async.wait_group 1;" ::: "memory");
        } else {
            asm volatile("cp.async.wait_group 0;" ::: "memory");
        }
        // Single barrier: (a) makes chunk kc visible to all warps,
        // (b) proves all warps finished computing chunk kc-1, whose stage
        //     (kc-1)%3 == (kc+2)%3 is the one the prefetch below overwrites.
        __syncthreads();

        if (kc + 2 < NCHUNK) {
            uint32_t st = base + ((kc + 2) % NSTAGE) * GSTAGE;
            const size_t k0 = (size_t)(kc + 2) * BKC;
            cp16(st + ldDst,             g_xhi + aBase + k0);
            cp16(st + GTILE + ldDst,     g_xlo + aBase + k0);
            cp16(st + 2 * GTILE + ldDst, g_Whi + bBase + k0);
            cp16(st + 3 * GTILE + ldDst, g_Wlo + bBase + k0);
            asm volatile("cp.async.commit_group;" ::: "memory");
        }

        const uint32_t stCur = base + (kc % NSTAGE) * GSTAGE;
        uint32_t bh[2][4], bl[2][4];
#pragma unroll
        for (int p = 0; p < 2; p++) {
            ldsm_x4(bh[p], stCur + 2 * GTILE + bOff[p]);
            ldsm_x4(bl[p], stCur + 3 * GTILE + bOff[p]);
        }
#pragma unroll
        for (int mi = 0; mi < 4; mi++) {
            uint32_t ah[4], al[4];
            ldsm_x4(ah, stCur + aOff[mi]);
            ldsm_x4(al, stCur + GTILE + aOff[mi]);
#pragma unroll
            for (int ni = 0; ni < 4; ni++) {
                const int p = ni >> 1, h = (ni & 1) * 2;
                mma_bf16(acc[mi][ni], ah, &bh[p][h]);
                mma_bf16(acc[mi][ni], ah, &bl[p][h]);
                mma_bf16(acc[mi][ni], al, &bh[p][h]);
            }
        }
    }

    // epilogue
    const bool isMlp = (nBase >= 512);
    const int rBase = tileM + warp_m * 64 + (lane >> 2);
    const int cBase = nBase + warp_n * 32 + 2 * (lane & 3);
#pragma unroll
    for (int mi = 0; mi < 4; mi++) {
#pragma unroll
        for (int half = 0; half < 2; half++) {
            const int row = rBase + mi * 16 + half * 8;
            if (row >= M) continue;
            float* dst = g_C1 + (size_t)row * 768;
#pragma unroll
            for (int ni = 0; ni < 4; ni++) {
                const int col = cBase + ni * 8;
                float v0 = acc[mi][ni][half * 2 + 0];
                float v1 = acc[mi][ni][half * 2 + 1];
                if (isMlp) {
                    v0 = tanhf(v0 + mlp1_b[col - 512]);
                    v1 = tanhf(v1 + mlp1_b[col - 511]);
                }
                *reinterpret_cast<float2*>(dst + col) = make_float2(v0, v1);
            }
        }
    }
}

// ---------------- SpMM 256-wide: one warp per edge ----------------
__global__ void spmm256(const int* __restrict__ rows,
                        const int* __restrict__ cols,
                        const float* __restrict__ vals,
                        int denseOff, int outOff, int E) {
    int w = (blockIdx.x * blockDim.x + threadIdx.x) >> 5;
    int lane = threadIdx.x & 31;
    if (w >= E) return;
    int r = __ldg(rows + w);
    int c = __ldg(cols + w);
    float v = __ldg(vals + w);
    const float* src = g_C1 + (size_t)c * 768 + denseOff;
    float* dst = g_S1 + (size_t)r * 512 + outOff;
#pragma unroll
    for (int p = 0; p < 2; p++) {
        int j = p * 128 + lane * 4;
        float4 s = *reinterpret_cast<const float4*>(src + j);
        s.x *= v; s.y *= v; s.z *= v; s.w *= v;
        asm volatile("red.global.add.v4.f32 [%0], {%1,%2,%3,%4};"
                     :: "l"(dst + j), "f"(s.x), "f"(s.y), "f"(s.z), "f"(s.w)
                     : "memory");
    }
}

// ---------------- attention fusion: one block (256 thr) per node ----------------
__global__ void fuse_att(const float* __restrict__ b1r1,
                         const float* __restrict__ b1r2,
                         const float* __restrict__ af) {
    int i = blockIdx.x;
    int h = threadIdx.x;
    int lane = h & 31, warp = h >> 5;

    float v1 = g_S1[(size_t)i * 512 + h] + b1r1[h];
    float v2 = g_S1[(size_t)i * 512 + 256 + h] + b1r2[h];
    float v3 = g_C1[(size_t)i * 768 + 512 + h];

    float p0 = v1 * af[h * 3 + 0] + v2 * af[(256 + h) * 3 + 0] + v3 * af[(512 + h) * 3 + 0];
    float p1 = v1 * af[h * 3 + 1] + v2 * af[(256 + h) * 3 + 1] + v3 * af[(512 + h) * 3 + 1];
    float p2 = v1 * af[h * 3 + 2] + v2 * af[(256 + h) * 3 + 2] + v3 * af[(512 + h) * 3 + 2];

#pragma unroll
    for (int off = 16; off; off >>= 1) {
        p0 += __shfl_xor_sync(0xffffffffu, p0, off);
        p1 += __shfl_xor_sync(0xffffffffu, p1, off);
        p2 += __shfl_xor_sync(0xffffffffu, p2, off);
    }
    __shared__ float red[8][3];
    if (lane == 0) { red[warp][0] = p0; red[warp][1] = p1; red[warp][2] = p2; }
    __syncthreads();

    float a0 = 0.f, a1 = 0.f, a2 = 0.f;
#pragma unroll
    for (int w = 0; w < 8; w++) { a0 += red[w][0]; a1 += red[w][1]; a2 += red[w][2]; }

    a0 = fabsf(a0); a1 = fabsf(a1); a2 = fabsf(a2);
    float m = fmaxf(a0, fmaxf(a1, a2));
    float e0 = __expf(a0 - m), e1 = __expf(a1 - m), e2 = __expf(a2 - m);
    float inv = 1.0f / (e0 + e1 + e2);

    g_X1[(size_t)i * 256 + h] = v1 * (e0 * inv) + v2 * (e1 * inv) + v3 * (e2 * inv);
}

// ---------------- GEMM2 fused: Z2 (r1,r2 cols) + out init ----------------
__global__ void gemm2_out(const float* __restrict__ W2r1,
                          const float* __restrict__ W2r2,
                          const float* __restrict__ mlp2_W,
                          const float* __restrict__ b2r1,
                          const float* __restrict__ b2r2,
                          const float* __restrict__ mlp2_b,
                          float* __restrict__ out, int M) {
    __shared__ float Ws[256 * 6];
    for (int t = threadIdx.x; t < 256 * 6; t += blockDim.x) {
        int k = t / 6, j = t % 6;
        float v;
        if (j < 2)      v = W2r1[k * 2 + j];
        else if (j < 4) v = W2r2[k * 2 + (j - 2)];
        else            v = mlp2_W[k * 2 + (j - 4)];
        Ws[t] = v;
    }
    __syncthreads();

    int warp = threadIdx.x >> 5, lane = threadIdx.x & 31;
    int row = blockIdx.x * 8 + warp;
    if (row >= M) return;

    float acc[6] = {0.f, 0.f, 0.f, 0.f, 0.f, 0.f};
    const float* xr = g_X1 + (size_t)row * 256;
    for (int k = lane; k < 256; k += 32) {
        float xv = xr[k];
#pragma unroll
        for (int j = 0; j < 6; j++) acc[j] = fmaf(xv, Ws[k * 6 + j], acc[j]);
    }
#pragma unroll
    for (int off = 16; off; off >>= 1)
#pragma unroll
        for (int j = 0; j < 6; j++) acc[j] += __shfl_xor_sync(0xffffffffu, acc[j], off);

    if (lane == 0) {
        float* z = g_Z2 + (size_t)row * 4;
        z[0] = acc[0]; z[1] = acc[1]; z[2] = acc[2]; z[3] = acc[3];
        out[row * 2 + 0] = b2r1[0] + b2r2[0] + tanhf(acc[4] + mlp2_b[0]);
        out[row * 2 + 1] = b2r1[1] + b2r2[1] + tanhf(acc[5] + mlp2_b[1]);
    }
}

__global__ void spmm2(const int* __restrict__ rows,
                      const int* __restrict__ cols,
                      const float* __restrict__ vals,
                      int zOff, float* __restrict__ out, int E) {
    int i = blockIdx.x * blockDim.x + threadIdx.x;
    if (i >= E) return;
    int r = __ldg(rows + i);
    int c = __ldg(cols + i);
    float v = __ldg(vals + i);
    float2 s = *reinterpret_cast<const float2*>(g_Z2 + (size_t)c * 4 + zOff);
    s.x *= v; s.y *= v;
    asm volatile("red.global.add.v2.f32 [%0], {%1,%2};"
                 :: "l"(out + (size_t)r * 2), "f"(s.x), "f"(s.y)
                 : "memory");
}

// ---------------- launch ----------------
extern "C" void kernel_launch(void* const* d_in, const int* in_sizes, int n_in,
                              void* d_out, int out_size) {
    const float* x        = (const float*)d_in[0];
    const int*   adj_rows = (const int*)d_in[1];
    const int*   adj_cols = (const int*)d_in[2];
    const float* adj_vals = (const float*)d_in[3];
    const int*   s_rows   = (const int*)d_in[4];
    const int*   s_cols   = (const int*)d_in[5];
    const float* s_vals   = (const float*)d_in[6];
    const float* W1r1     = (const float*)d_in[7];
    const float* b1r1     = (const float*)d_in[8];
    const float* W1r2     = (const float*)d_in[9];
    const float* b1r2     = (const float*)d_in[10];
    const float* mlp1_W   = (const float*)d_in[11];
    const float* mlp1_b   = (const float*)d_in[12];
    const float* af1_w    = (const float*)d_in[13];
    const float* W2r1     = (const float*)d_in[14];
    const float* b2r1     = (const float*)d_in[15];
    const float* W2r2     = (const float*)d_in[16];
    const float* b2r2     = (const float*)d_in[17];
    const float* mlp2_W   = (const float*)d_in[18];
    const float* mlp2_b   = (const float*)d_in[19];
    float* out = (float*)d_out;

    const int E = in_sizes[1];
    const int M = N_NODES;

    cudaFuncSetAttribute(gemm1_mma, cudaFuncAttributeMaxDynamicSharedMemorySize, GSMEM);

    // prep
    split_x_zero<<<1184, 256>>>(x);
    pack_w1split<<<(768 * 768 + 255) / 256, 256>>>(W1r1, W1r2, mlp1_W);

    // layer 1 big GEMM on tensor cores (HMMA)
    dim3 g1(6, (M + 127) / 128);
    gemm1_mma<<<g1, 256, GSMEM>>>(mlp1_b, M);

    // layer 1 spmms
    int spmmBlocks = (E * 32 + 255) / 256;
    spmm256<<<spmmBlocks, 256>>>(adj_rows, adj_cols, adj_vals, 0,   0,   E);
    spmm256<<<spmmBlocks, 256>>>(s_rows,   s_cols,   s_vals,   256, 256, E);

    // attention fusion
    fuse_att<<<M, 256>>>(b1r1, b1r2, af1_w);

    // layer 2
    gemm2_out<<<(M + 7) / 8, 256>>>(W2r1, W2r2, mlp2_W, b2r1, b2r2, mlp2_b, out, M);
    spmm2<<<(E + 255) / 256, 256>>>(adj_rows, adj_cols, adj_vals, 0, out, E);
    spmm2<<<(E + 255) / 256, 256>>>(s_rows,   s_cols,   s_vals,   2, out, E);
}

// round 7
// speedup vs baseline: 1.8416x; 1.1287x over previous
#include <cuda_runtime.h>
#include <cuda_bf16.h>
#include <math.h>
#include <stdint.h>

#define N_NODES 50000
#define D_IN    768
#define NHID    256
#define ECAP    128                      // slots per row-bucket (P(overflow) ~ e^-49)

// ---------------- device scratch (no allocations allowed) ----------------
__device__ float g_C1[(size_t)N_NODES * 768];   // x @ [W1r1 | W1r2 | mlp1_W]; mlp block tanh'd
__device__ float g_X1[(size_t)N_NODES * 256];   // fused layer-1 output
__device__ float g_Z2[(size_t)N_NODES * 4];     // x1 @ [W2r1 | W2r2]

// bf16 split operands for the tensor-core GEMM
__device__ __nv_bfloat16 g_xhi[(size_t)N_NODES * 768];
__device__ __nv_bfloat16 g_xlo[(size_t)N_NODES * 768];
__device__ __nv_bfloat16 g_Whi[768 * 768];      // transposed: [n][k] = Wcat[k][n]
__device__ __nv_bfloat16 g_Wlo[768 * 768];

// bucketed-CSR edge storage: per destination row, up to ECAP (col,val) pairs
__device__ int    g_cnt_adj[N_NODES];
__device__ int    g_cnt_s[N_NODES];
__device__ float2 g_edge_adj[(size_t)N_NODES * ECAP];   // .x = col (int bits), .y = val
__device__ float2 g_edge_s[(size_t)N_NODES * ECAP];

// ================= helpers =================
__device__ __forceinline__ uint32_t smem_u32(const void* p) {
    uint32_t a;
    asm("{ .reg .u64 t; cvta.to.shared.u64 t, %1; cvt.u32.u64 %0, t; }" : "=r"(a) : "l"(p));
    return a;
}
__device__ __forceinline__ void cp16(uint32_t dst, const void* src) {
    asm volatile("cp.async.cg.shared.global [%0], [%1], 16;" :: "r"(dst), "l"(src));
}
__device__ __forceinline__ void ldsm_x4(uint32_t* r, uint32_t addr) {
    asm volatile("ldmatrix.sync.aligned.m8n8.x4.shared.b16 {%0,%1,%2,%3}, [%4];"
                 : "=r"(r[0]), "=r"(r[1]), "=r"(r[2]), "=r"(r[3]) : "r"(addr));
}
__device__ __forceinline__ void mma_bf16(float* c, const uint32_t* a, const uint32_t* b) {
    asm volatile("mma.sync.aligned.m16n8k16.row.col.f32.bf16.bf16.f32 "
                 "{%0,%1,%2,%3}, {%4,%5,%6,%7}, {%8,%9}, {%0,%1,%2,%3};"
                 : "+f"(c[0]), "+f"(c[1]), "+f"(c[2]), "+f"(c[3])
                 : "r"(a[0]), "r"(a[1]), "r"(a[2]), "r"(a[3]), "r"(b[0]), "r"(b[1]));
}

// ---------------- prep: split x into bf16 hi/lo AND zero edge counters ----------------
__global__ void split_x_zero(const float* __restrict__ x) {
    size_t stride = (size_t)gridDim.x * blockDim.x;
    size_t i = (size_t)blockIdx.x * blockDim.x + threadIdx.x;
    const size_t totalX = (size_t)N_NODES * 768;
    for (size_t j = i; j < totalX; j += stride) {
        float v = x[j];
        __nv_bfloat16 hi = __float2bfloat16(v);
        g_xhi[j] = hi;
        g_xlo[j] = __float2bfloat16(v - __bfloat162float(hi));
    }
    for (size_t j = i; j < N_NODES; j += stride) {
        g_cnt_adj[j] = 0;
        g_cnt_s[j] = 0;
    }
}

// ---------------- prep: pack + transpose + split layer-1 weights ----------------
__global__ void pack_w1split(const float* __restrict__ W1r1,
                             const float* __restrict__ W1r2,
                             const float* __restrict__ mlp1_W) {
    int idx = blockIdx.x * blockDim.x + threadIdx.x;
    if (idx >= 768 * 768) return;
    int n = idx / 768, k = idx % 768;     // output [n][k] = W[k][n]
    float v;
    if (n < 256)       v = W1r1[k * 256 + n];
    else if (n < 512)  v = W1r2[k * 256 + (n - 256)];
    else               v = mlp1_W[k * 256 + (n - 512)];
    __nv_bfloat16 hi = __float2bfloat16(v);
    g_Whi[idx] = hi;
    g_Wlo[idx] = __float2bfloat16(v - __bfloat162float(hi));
}

// ---------------- build row buckets for both edge sets ----------------
__global__ void build_buckets(const int* __restrict__ adj_rows,
                              const int* __restrict__ adj_cols,
                              const float* __restrict__ adj_vals,
                              const int* __restrict__ s_rows,
                              const int* __restrict__ s_cols,
                              const float* __restrict__ s_vals,
                              int E) {
    int idx = blockIdx.x * blockDim.x + threadIdx.x;
    if (idx < E) {
        int r = adj_rows[idx];
        int slot = atomicAdd(&g_cnt_adj[r], 1);
        if (slot < ECAP)
            g_edge_adj[(size_t)r * ECAP + slot] =
                make_float2(__int_as_float(adj_cols[idx]), adj_vals[idx]);
    } else if (idx < 2 * E) {
        int j = idx - E;
        int r = s_rows[j];
        int slot = atomicAdd(&g_cnt_s[r], 1);
        if (slot < ECAP)
            g_edge_s[(size_t)r * ECAP + slot] =
                make_float2(__int_as_float(s_cols[j]), s_vals[j]);
    }
}

// ================= GEMM1 via mma.sync (HMMA, bf16 split) =================
#define BKC 16
#define ROWB 48
#define GTILE (128 * ROWB)
#define GSTAGE (4 * GTILE)
#define NSTAGE 3
#define GSMEM  (NSTAGE * GSTAGE)
#define NCHUNK (768 / BKC)

__global__ __launch_bounds__(256, 2)
void gemm1_mma(const float* __restrict__ mlp1_b, int M) {
    extern __shared__ char dsm[];
    const uint32_t base = smem_u32(dsm);

    const int tid = threadIdx.x;
    const int lane = tid & 31, wid = tid >> 5;
    const int warp_m = wid >> 2;
    const int warp_n = wid & 3;
    const int tileM = blockIdx.y * 128;
    const int nBase = blockIdx.x * 128;

    const int ldR = tid >> 1;
    const int ldG = tid & 1;
    int srcRowA = tileM + ldR; if (srcRowA >= M) srcRowA = M - 1;
    const uint32_t ldDst = ldR * ROWB + ldG * 16;
    const size_t aBase = (size_t)srcRowA * 768 + ldG * 8;
    const size_t bBase = (size_t)(nBase + ldR) * 768 + ldG * 8;

    const int aRow = warp_m * 64 + (lane & 15);
    const int aK   = (lane >> 4) * 8;
    uint32_t aOff[4];
#pragma unroll
    for (int mi = 0; mi < 4; mi++) aOff[mi] = (uint32_t)((aRow + mi * 16) * ROWB + aK * 2);
    const int bN = warp_n * 32 + (lane & 7) + ((lane >> 4) << 3);
    const int bK = ((lane >> 3) & 1) * 8;
    uint32_t bOff[2];
#pragma unroll
    for (int p = 0; p < 2; p++) bOff[p] = (uint32_t)((bN + p * 16) * ROWB + bK * 2);

    float acc[4][4][4];
#pragma unroll
    for (int mi = 0; mi < 4; mi++)
#pragma unroll
        for (int ni = 0; ni < 4; ni++)
#pragma unroll
            for (int r = 0; r < 4; r++) acc[mi][ni][r] = 0.f;

#pragma unroll
    for (int pc = 0; pc < 2; pc++) {
        uint32_t st = base + pc * GSTAGE;
        const size_t k0 = (size_t)pc * BKC;
        cp16(st + ldDst,             g_xhi + aBase + k0);
        cp16(st + GTILE + ldDst,     g_xlo + aBase + k0);
        cp16(st + 2 * GTILE + ldDst, g_Whi + bBase + k0);
        cp16(st + 3 * GTILE + ldDst, g_Wlo + bBase + k0);
        asm volatile("cp.async.commit_group;" ::: "memory");
    }

    for (int kc = 0; kc < NCHUNK; ++kc) {
        if (kc + 1 < NCHUNK) {
            asm volatile("cp.async.wait_group 1;" ::: "memory");
        } else {
            asm volatile("cp.async.wait_group 0;" ::: "memory");
        }
        __syncthreads();

        if (kc + 2 < NCHUNK) {
            uint32_t st = base + ((kc + 2) % NSTAGE) * GSTAGE;
            const size_t k0 = (size_t)(kc + 2) * BKC;
            cp16(st + ldDst,             g_xhi + aBase + k0);
            cp16(st + GTILE + ldDst,     g_xlo + aBase + k0);
            cp16(st + 2 * GTILE + ldDst, g_Whi + bBase + k0);
            cp16(st + 3 * GTILE + ldDst, g_Wlo + bBase + k0);
            asm volatile("cp.async.commit_group;" ::: "memory");
        }

        const uint32_t stCur = base + (kc % NSTAGE) * GSTAGE;
        uint32_t bh[2][4], bl[2][4];
#pragma unroll
        for (int p = 0; p < 2; p++) {
            ldsm_x4(bh[p], stCur + 2 * GTILE + bOff[p]);
            ldsm_x4(bl[p], stCur + 3 * GTILE + bOff[p]);
        }
#pragma unroll
        for (int mi = 0; mi < 4; mi++) {
            uint32_t ah[4], al[4];
            ldsm_x4(ah, stCur + aOff[mi]);
            ldsm_x4(al, stCur + GTILE + aOff[mi]);
#pragma unroll
            for (int ni = 0; ni < 4; ni++) {
                const int p = ni >> 1, h = (ni & 1) * 2;
                mma_bf16(acc[mi][ni], ah, &bh[p][h]);
                mma_bf16(acc[mi][ni], ah, &bl[p][h]);
                mma_bf16(acc[mi][ni], al, &bh[p][h]);
            }
        }
    }

    const bool isMlp = (nBase >= 512);
    const int rBase = tileM + warp_m * 64 + (lane >> 2);
    const int cBase = nBase + warp_n * 32 + 2 * (lane & 3);
#pragma unroll
    for (int mi = 0; mi < 4; mi++) {
#pragma unroll
        for (int half = 0; half < 2; half++) {
            const int row = rBase + mi * 16 + half * 8;
            if (row >= M) continue;
            float* dst = g_C1 + (size_t)row * 768;
#pragma unroll
            for (int ni = 0; ni < 4; ni++) {
                const int col = cBase + ni * 8;
                float v0 = acc[mi][ni][half * 2 + 0];
                float v1 = acc[mi][ni][half * 2 + 1];
                if (isMlp) {
                    v0 = tanhf(v0 + mlp1_b[col - 512]);
                    v1 = tanhf(v1 + mlp1_b[col - 511]);
                }
                *reinterpret_cast<float2*>(dst + col) = make_float2(v0, v1);
            }
        }
    }
}

// ---------------- fused layer-1 aggregation: gather both branches + attention ----------------
// One 256-thread block per node. Thread h owns hidden unit h.
__global__ __launch_bounds__(256)
void gather_att(const float* __restrict__ b1r1,
                const float* __restrict__ b1r2,
                const float* __restrict__ af) {
    const int i = blockIdx.x;
    const int h = threadIdx.x;
    const int lane = h & 31, warp = h >> 5;

    // branch 1: adj gather over C1 cols [0,256)
    float v1 = 0.f;
    {
        const int n = min(g_cnt_adj[i], ECAP);
        const float2* eb = g_edge_adj + (size_t)i * ECAP;
        for (int e = 0; e < n; e++) {
            float2 ev = __ldg(eb + e);
            int c = __float_as_int(ev.x);
            v1 += ev.y * __ldg(g_C1 + (size_t)c * 768 + h);
        }
        v1 += b1r1[h];
    }
    // branch 2: s gather over C1 cols [256,512)
    float v2 = 0.f;
    {
        const int n = min(g_cnt_s[i], ECAP);
        const float2* eb = g_edge_s + (size_t)i * ECAP;
        for (int e = 0; e < n; e++) {
            float2 ev = __ldg(eb + e);
            int c = __float_as_int(ev.x);
            v2 += ev.y * __ldg(g_C1 + (size_t)c * 768 + 256 + h);
        }
        v2 += b1r2[h];
    }
    // branch 3: tanh mlp (already computed in gemm1 epilogue)
    float v3 = g_C1[(size_t)i * 768 + 512 + h];

    // attention fusion
    float p0 = v1 * af[h * 3 + 0] + v2 * af[(256 + h) * 3 + 0] + v3 * af[(512 + h) * 3 + 0];
    float p1 = v1 * af[h * 3 + 1] + v2 * af[(256 + h) * 3 + 1] + v3 * af[(512 + h) * 3 + 1];
    float p2 = v1 * af[h * 3 + 2] + v2 * af[(256 + h) * 3 + 2] + v3 * af[(512 + h) * 3 + 2];

#pragma unroll
    for (int off = 16; off; off >>= 1) {
        p0 += __shfl_xor_sync(0xffffffffu, p0, off);
        p1 += __shfl_xor_sync(0xffffffffu, p1, off);
        p2 += __shfl_xor_sync(0xffffffffu, p2, off);
    }
    __shared__ float red[8][3];
    if (lane == 0) { red[warp][0] = p0; red[warp][1] = p1; red[warp][2] = p2; }
    __syncthreads();

    float a0 = 0.f, a1 = 0.f, a2 = 0.f;
#pragma unroll
    for (int w = 0; w < 8; w++) { a0 += red[w][0]; a1 += red[w][1]; a2 += red[w][2]; }

    a0 = fabsf(a0); a1 = fabsf(a1); a2 = fabsf(a2);
    float m = fmaxf(a0, fmaxf(a1, a2));
    float e0 = __expf(a0 - m), e1 = __expf(a1 - m), e2 = __expf(a2 - m);
    float inv = 1.0f / (e0 + e1 + e2);

    g_X1[(size_t)i * 256 + h] = v1 * (e0 * inv) + v2 * (e1 * inv) + v3 * (e2 * inv);
}

// ---------------- GEMM2 fused: Z2 (r1,r2 cols) + out init ----------------
__global__ void gemm2_out(const float* __restrict__ W2r1,
                          const float* __restrict__ W2r2,
                          const float* __restrict__ mlp2_W,
                          const float* __restrict__ b2r1,
                          const float* __restrict__ b2r2,
                          const float* __restrict__ mlp2_b,
                          float* __restrict__ out, int M) {
    __shared__ float Ws[256 * 6];
    for (int t = threadIdx.x; t < 256 * 6; t += blockDim.x) {
        int k = t / 6, j = t % 6;
        float v;
        if (j < 2)      v = W2r1[k * 2 + j];
        else if (j < 4) v = W2r2[k * 2 + (j - 2)];
        else            v = mlp2_W[k * 2 + (j - 4)];
        Ws[t] = v;
    }
    __syncthreads();

    int warp = threadIdx.x >> 5, lane = threadIdx.x & 31;
    int row = blockIdx.x * 8 + warp;
    if (row >= M) return;

    float acc[6] = {0.f, 0.f, 0.f, 0.f, 0.f, 0.f};
    const float* xr = g_X1 + (size_t)row * 256;
    for (int k = lane; k < 256; k += 32) {
        float xv = xr[k];
#pragma unroll
        for (int j = 0; j < 6; j++) acc[j] = fmaf(xv, Ws[k * 6 + j], acc[j]);
    }
#pragma unroll
    for (int off = 16; off; off >>= 1)
#pragma unroll
        for (int j = 0; j < 6; j++) acc[j] += __shfl_xor_sync(0xffffffffu, acc[j], off);

    if (lane == 0) {
        float* z = g_Z2 + (size_t)row * 4;
        z[0] = acc[0]; z[1] = acc[1]; z[2] = acc[2]; z[3] = acc[3];
        out[row * 2 + 0] = b2r1[0] + b2r2[0] + tanhf(acc[4] + mlp2_b[0]);
        out[row * 2 + 1] = b2r1[1] + b2r2[1] + tanhf(acc[5] + mlp2_b[1]);
    }
}

// ---------------- layer-2 aggregation: warp-per-node gather, no atomics ----------------
__global__ __launch_bounds__(256)
void gather2_out(float* __restrict__ out, int M) {
    const int warp = threadIdx.x >> 5, lane = threadIdx.x & 31;
    const int i = blockIdx.x * 8 + warp;
    if (i >= M) return;

    float s0 = 0.f, s1 = 0.f;
    {
        const int n = min(g_cnt_adj[i], ECAP);
        const float2* eb = g_edge_adj + (size_t)i * ECAP;
        for (int e = lane; e < n; e += 32) {
            float2 ev = __ldg(eb + e);
            int c = __float_as_int(ev.x);
            float2 z = *reinterpret_cast<const float2*>(g_Z2 + (size_t)c * 4);
            s0 += ev.y * z.x;
            s1 += ev.y * z.y;
        }
    }
    {
        const int n = min(g_cnt_s[i], ECAP);
        const float2* eb = g_edge_s + (size_t)i * ECAP;
        for (int e = lane; e < n; e += 32) {
            float2 ev = __ldg(eb + e);
            int c = __float_as_int(ev.x);
            float2 z = *reinterpret_cast<const float2*>(g_Z2 + (size_t)c * 4 + 2);
            s0 += ev.y * z.x;
            s1 += ev.y * z.y;
        }
    }
#pragma unroll
    for (int off = 16; off; off >>= 1) {
        s0 += __shfl_xor_sync(0xffffffffu, s0, off);
        s1 += __shfl_xor_sync(0xffffffffu, s1, off);
    }
    if (lane == 0) {
        out[i * 2 + 0] += s0;
        out[i * 2 + 1] += s1;
    }
}

// ---------------- launch ----------------
extern "C" void kernel_launch(void* const* d_in, const int* in_sizes, int n_in,
                              void* d_out, int out_size) {
    const float* x        = (const float*)d_in[0];
    const int*   adj_rows = (const int*)d_in[1];
    const int*   adj_cols = (const int*)d_in[2];
    const float* adj_vals = (const float*)d_in[3];
    const int*   s_rows   = (const int*)d_in[4];
    const int*   s_cols   = (const int*)d_in[5];
    const float* s_vals   = (const float*)d_in[6];
    const float* W1r1     = (const float*)d_in[7];
    const float* b1r1     = (const float*)d_in[8];
    const float* W1r2     = (const float*)d_in[9];
    const float* b1r2     = (const float*)d_in[10];
    const float* mlp1_W   = (const float*)d_in[11];
    const float* mlp1_b   = (const float*)d_in[12];
    const float* af1_w    = (const float*)d_in[13];
    const float* W2r1     = (const float*)d_in[14];
    const float* b2r1     = (const float*)d_in[15];
    const float* W2r2     = (const float*)d_in[16];
    const float* b2r2     = (const float*)d_in[17];
    const float* mlp2_W   = (const float*)d_in[18];
    const float* mlp2_b   = (const float*)d_in[19];
    float* out = (float*)d_out;

    const int E = in_sizes[1];
    const int M = N_NODES;

    cudaFuncSetAttribute(gemm1_mma, cudaFuncAttributeMaxDynamicSharedMemorySize, GSMEM);

    // prep
    split_x_zero<<<1184, 256>>>(x);
    pack_w1split<<<(768 * 768 + 255) / 256, 256>>>(W1r1, W1r2, mlp1_W);
    build_buckets<<<(2 * E + 255) / 256, 256>>>(adj_rows, adj_cols, adj_vals,
                                                s_rows, s_cols, s_vals, E);

    // layer 1 big GEMM on tensor cores (HMMA)
    dim3 g1(6, (M + 127) / 128);
    gemm1_mma<<<g1, 256, GSMEM>>>(mlp1_b, M);

    // layer 1 aggregation + attention fusion (gather, no atomics)
    gather_att<<<M, 256>>>(b1r1, b1r2, af1_w);

    // layer 2
    gemm2_out<<<(M + 7) / 8, 256>>>(W2r1, W2r2, mlp2_W, b2r1, b2r2, mlp2_b, out, M);
    gather2_out<<<(M + 7) / 8, 256>>>(out, M);
}

// round 8
// speedup vs baseline: 2.3182x; 1.2588x over previous
#include <cuda_runtime.h>
#include <cuda_fp16.h>
#include <math.h>
#include <stdint.h>

#define N_NODES 50000
#define D_IN    768
#define NHID    256
#define ECAP    128                      // slots per row-bucket (P(overflow) ~ e^-49)

// ---------------- device scratch (no allocations allowed) ----------------
__device__ float g_C1[(size_t)N_NODES * 768];   // x @ [W1r1 | W1r2 | mlp1_W]; mlp block tanh'd
__device__ float g_X1[(size_t)N_NODES * 256];   // fused layer-1 output
__device__ float g_Z2[(size_t)N_NODES * 4];     // x1 @ [W2r1 | W2r2]

// fp16 operands for the tensor-core GEMM: x rounded to fp16, W split hi+lo
__device__ __half g_xh[(size_t)N_NODES * 768];
__device__ __half g_Whi[768 * 768];             // transposed: [n][k] = Wcat[k][n]
__device__ __half g_Wlo[768 * 768];

// bucketed-CSR edge storage: per destination row, up to ECAP (col,val) pairs
__device__ int    g_cnt_adj[N_NODES];
__device__ int    g_cnt_s[N_NODES];
__device__ float2 g_edge_adj[(size_t)N_NODES * ECAP];   // .x = col (int bits), .y = val
__device__ float2 g_edge_s[(size_t)N_NODES * ECAP];

// ================= helpers =================
__device__ __forceinline__ uint32_t smem_u32(const void* p) {
    uint32_t a;
    asm("{ .reg .u64 t; cvta.to.shared.u64 t, %1; cvt.u32.u64 %0, t; }" : "=r"(a) : "l"(p));
    return a;
}
__device__ __forceinline__ void cp16(uint32_t dst, const void* src) {
    asm volatile("cp.async.cg.shared.global [%0], [%1], 16;" :: "r"(dst), "l"(src));
}
__device__ __forceinline__ void ldsm_x4(uint32_t* r, uint32_t addr) {
    asm volatile("ldmatrix.sync.aligned.m8n8.x4.shared.b16 {%0,%1,%2,%3}, [%4];"
                 : "=r"(r[0]), "=r"(r[1]), "=r"(r[2]), "=r"(r[3]) : "r"(addr));
}
__device__ __forceinline__ void mma_f16(float* c, const uint32_t* a, const uint32_t* b) {
    asm volatile("mma.sync.aligned.m16n8k16.row.col.f32.f16.f16.f32 "
                 "{%0,%1,%2,%3}, {%4,%5,%6,%7}, {%8,%9}, {%0,%1,%2,%3};"
                 : "+f"(c[0]), "+f"(c[1]), "+f"(c[2]), "+f"(c[3])
                 : "r"(a[0]), "r"(a[1]), "r"(a[2]), "r"(a[3]), "r"(b[0]), "r"(b[1]));
}

// ---------------- prep: x -> fp16 AND zero edge counters ----------------
__global__ void split_x_zero(const float* __restrict__ x) {
    size_t stride = (size_t)gridDim.x * blockDim.x;
    size_t i = (size_t)blockIdx.x * blockDim.x + threadIdx.x;
    const size_t totalX = (size_t)N_NODES * 768;
    for (size_t j = i; j < totalX; j += stride)
        g_xh[j] = __float2half_rn(x[j]);
    for (size_t j = i; j < N_NODES; j += stride) {
        g_cnt_adj[j] = 0;
        g_cnt_s[j] = 0;
    }
}

// ---------------- prep: pack + transpose + fp16-split layer-1 weights ----------------
__global__ void pack_w1split(const float* __restrict__ W1r1,
                             const float* __restrict__ W1r2,
                             const float* __restrict__ mlp1_W) {
    int idx = blockIdx.x * blockDim.x + threadIdx.x;
    if (idx >= 768 * 768) return;
    int n = idx / 768, k = idx % 768;     // output [n][k] = W[k][n]
    float v;
    if (n < 256)       v = W1r1[k * 256 + n];
    else if (n < 512)  v = W1r2[k * 256 + (n - 256)];
    else               v = mlp1_W[k * 256 + (n - 512)];
    __half hi = __float2half_rn(v);
    g_Whi[idx] = hi;
    g_Wlo[idx] = __float2half_rn(v - __half2float(hi));
}

// ---------------- build row buckets for both edge sets ----------------
__global__ void build_buckets(const int* __restrict__ adj_rows,
                              const int* __restrict__ adj_cols,
                              const float* __restrict__ adj_vals,
                              const int* __restrict__ s_rows,
                              const int* __restrict__ s_cols,
                              const float* __restrict__ s_vals,
                              int E) {
    int idx = blockIdx.x * blockDim.x + threadIdx.x;
    if (idx < E) {
        int r = adj_rows[idx];
        int slot = atomicAdd(&g_cnt_adj[r], 1);
        if (slot < ECAP)
            g_edge_adj[(size_t)r * ECAP + slot] =
                make_float2(__int_as_float(adj_cols[idx]), adj_vals[idx]);
    } else if (idx < 2 * E) {
        int j = idx - E;
        int r = s_rows[j];
        int slot = atomicAdd(&g_cnt_s[r], 1);
        if (slot < ECAP)
            g_edge_s[(size_t)r * ECAP + slot] =
                make_float2(__int_as_float(s_cols[j]), s_vals[j]);
    }
}

// ================= GEMM1 via mma.sync (HMMA fp16, 2 products) =================
// C1[M x 768] = x @ Wcat,  computed as  xh·Whi + xh·Wlo  (x rounded to fp16).
// CTA 128x128, 8 warps (2x4, 64x32 warp tiles), BK=16.
// 4-stage pipeline, chunk c -> stage c%4, prefetch distance 3, ONE barrier/iter.
#define BKC 16
#define ROWB 48                         // padded row stride in bytes (24 fp16)
#define GTILE (128 * ROWB)              // 6144 B per operand tile
#define GSTAGE (3 * GTILE)              // A, Bhi, Blo = 18432 B
#define NSTAGE 4
#define GSMEM  (NSTAGE * GSTAGE)        // 73728 B (needs opt-in attribute)
#define NCHUNK (768 / BKC)              // 48

__global__ __launch_bounds__(256, 2)
void gemm1_mma(const float* __restrict__ mlp1_b, int M) {
    extern __shared__ char dsm[];
    const uint32_t base = smem_u32(dsm);

    const int tid = threadIdx.x;
    const int lane = tid & 31, wid = tid >> 5;
    const int warp_m = wid >> 2;
    const int warp_n = wid & 3;
    const int tileM = blockIdx.y * 128;
    const int nBase = blockIdx.x * 128;

    // cp.async per-thread assignment: one 16B chunk per operand tile
    const int ldR = tid >> 1;
    const int ldG = tid & 1;
    int srcRowA = tileM + ldR; if (srcRowA >= M) srcRowA = M - 1;
    const uint32_t ldDst = ldR * ROWB + ldG * 16;
    const size_t aBase = (size_t)srcRowA * 768 + ldG * 8;
    const size_t bBase = (size_t)(nBase + ldR) * 768 + ldG * 8;

    // ldmatrix per-thread source offsets
    const int aRow = warp_m * 64 + (lane & 15);
    const int aK   = (lane >> 4) * 8;
    uint32_t aOff[4];
#pragma unroll
    for (int mi = 0; mi < 4; mi++) aOff[mi] = (uint32_t)((aRow + mi * 16) * ROWB + aK * 2);
    const int bN = warp_n * 32 + (lane & 7) + ((lane >> 4) << 3);
    const int bK = ((lane >> 3) & 1) * 8;
    uint32_t bOff[2];
#pragma unroll
    for (int p = 0; p < 2; p++) bOff[p] = (uint32_t)((bN + p * 16) * ROWB + bK * 2);

    float acc[4][4][4];
#pragma unroll
    for (int mi = 0; mi < 4; mi++)
#pragma unroll
        for (int ni = 0; ni < 4; ni++)
#pragma unroll
            for (int r = 0; r < 4; r++) acc[mi][ni][r] = 0.f;

    // prologue: chunks 0,1,2 -> stages 0,1,2
#pragma unroll
    for (int pc = 0; pc < 3; pc++) {
        uint32_t st = base + pc * GSTAGE;
        const size_t k0 = (size_t)pc * BKC;
        cp16(st + ldDst,             g_xh  + aBase + k0);
        cp16(st + GTILE + ldDst,     g_Whi + bBase + k0);
        cp16(st + 2 * GTILE + ldDst, g_Wlo + bBase + k0);
        asm volatile("cp.async.commit_group;" ::: "memory");
    }

    for (int kc = 0; kc < NCHUNK; ++kc) {
        // chunk kc must be resident; up to 2 newer chunks may stay in flight
        if (kc + 2 < NCHUNK) {
            asm volatile("cp.async.wait_group 2;" ::: "memory");
        } else if (kc + 1 < NCHUNK) {
            asm volatile("cp.async.wait_group 1;" ::: "memory");
        } else {
            asm volatile("cp.async.wait_group 0;" ::: "memory");
        }
        // Single barrier: (a) chunk kc visible to all warps, (b) all warps done
        // with chunk kc-1, whose stage (kc-1)%4 == (kc+3)%4 is overwritten below.
        __syncthreads();

        if (kc + 3 < NCHUNK) {
            uint32_t st = base + ((kc + 3) % NSTAGE) * GSTAGE;
            const size_t k0 = (size_t)(kc + 3) * BKC;
            cp16(st + ldDst,             g_xh  + aBase + k0);
            cp16(st + GTILE + ldDst,     g_Whi + bBase + k0);
            cp16(st + 2 * GTILE + ldDst, g_Wlo + bBase + k0);
            asm volatile("cp.async.commit_group;" ::: "memory");
        }

        const uint32_t stCur = base + (kc % NSTAGE) * GSTAGE;
        uint32_t bh[2][4], bl[2][4];
#pragma unroll
        for (int p = 0; p < 2; p++) {
            ldsm_x4(bh[p], stCur + GTILE + bOff[p]);
            ldsm_x4(bl[p], stCur + 2 * GTILE + bOff[p]);
        }
#pragma unroll
        for (int mi = 0; mi < 4; mi++) {
            uint32_t ah[4];
            ldsm_x4(ah, stCur + aOff[mi]);
#pragma unroll
            for (int ni = 0; ni < 4; ni++) {
                const int p = ni >> 1, h = (ni & 1) * 2;
                mma_f16(acc[mi][ni], ah, &bh[p][h]);
                mma_f16(acc[mi][ni], ah, &bl[p][h]);
            }
        }
    }

    // epilogue
    const bool isMlp = (nBase >= 512);
    const int rBase = tileM + warp_m * 64 + (lane >> 2);
    const int cBase = nBase + warp_n * 32 + 2 * (lane & 3);
#pragma unroll
    for (int mi = 0; mi < 4; mi++) {
#pragma unroll
        for (int half = 0; half < 2; half++) {
            const int row = rBase + mi * 16 + half * 8;
            if (row >= M) continue;
            float* dst = g_C1 + (size_t)row * 768;
#pragma unroll
            for (int ni = 0; ni < 4; ni++) {
                const int col = cBase + ni * 8;
                float v0 = acc[mi][ni][half * 2 + 0];
                float v1 = acc[mi][ni][half * 2 + 1];
                if (isMlp) {
                    v0 = tanhf(v0 + mlp1_b[col - 512]);
                    v1 = tanhf(v1 + mlp1_b[col - 511]);
                }
                *reinterpret_cast<float2*>(dst + col) = make_float2(v0, v1);
            }
        }
    }
}

// ---------------- fused layer-1 aggregation: gather both branches + attention ----------------
__global__ __launch_bounds__(256)
void gather_att(const float* __restrict__ b1r1,
                const float* __restrict__ b1r2,
                const float* __restrict__ af) {
    const int i = blockIdx.x;
    const int h = threadIdx.x;
    const int lane = h & 31, warp = h >> 5;

    float v1 = 0.f;
    {
        const int n = min(g_cnt_adj[i], ECAP);
        const float2* eb = g_edge_adj + (size_t)i * ECAP;
        for (int e = 0; e < n; e++) {
            float2 ev = __ldg(eb + e);
            int c = __float_as_int(ev.x);
            v1 += ev.y * __ldg(g_C1 + (size_t)c * 768 + h);
        }
        v1 += b1r1[h];
    }
    float v2 = 0.f;
    {
        const int n = min(g_cnt_s[i], ECAP);
        const float2* eb = g_edge_s + (size_t)i * ECAP;
        for (int e = 0; e < n; e++) {
            float2 ev = __ldg(eb + e);
            int c = __float_as_int(ev.x);
            v2 += ev.y * __ldg(g_C1 + (size_t)c * 768 + 256 + h);
        }
        v2 += b1r2[h];
    }
    float v3 = g_C1[(size_t)i * 768 + 512 + h];

    float p0 = v1 * af[h * 3 + 0] + v2 * af[(256 + h) * 3 + 0] + v3 * af[(512 + h) * 3 + 0];
    float p1 = v1 * af[h * 3 + 1] + v2 * af[(256 + h) * 3 + 1] + v3 * af[(512 + h) * 3 + 1];
    float p2 = v1 * af[h * 3 + 2] + v2 * af[(256 + h) * 3 + 2] + v3 * af[(512 + h) * 3 + 2];

#pragma unroll
    for (int off = 16; off; off >>= 1) {
        p0 += __shfl_xor_sync(0xffffffffu, p0, off);
        p1 += __shfl_xor_sync(0xffffffffu, p1, off);
        p2 += __shfl_xor_sync(0xffffffffu, p2, off);
    }
    __shared__ float red[8][3];
    if (lane == 0) { red[warp][0] = p0; red[warp][1] = p1; red[warp][2] = p2; }
    __syncthreads();

    float a0 = 0.f, a1 = 0.f, a2 = 0.f;
#pragma unroll
    for (int w = 0; w < 8; w++) { a0 += red[w][0]; a1 += red[w][1]; a2 += red[w][2]; }

    a0 = fabsf(a0); a1 = fabsf(a1); a2 = fabsf(a2);
    float m = fmaxf(a0, fmaxf(a1, a2));
    float e0 = __expf(a0 - m), e1 = __expf(a1 - m), e2 = __expf(a2 - m);
    float inv = 1.0f / (e0 + e1 + e2);

    g_X1[(size_t)i * 256 + h] = v1 * (e0 * inv) + v2 * (e1 * inv) + v3 * (e2 * inv);
}

// ---------------- GEMM2 fused: Z2 (r1,r2 cols) + out init ----------------
__global__ void gemm2_out(const float* __restrict__ W2r1,
                          const float* __restrict__ W2r2,
                          const float* __restrict__ mlp2_W,
                          const float* __restrict__ b2r1,
                          const float* __restrict__ b2r2,
                          const float* __restrict__ mlp2_b,
                          float* __restrict__ out, int M) {
    __shared__ float Ws[256 * 6];
    for (int t = threadIdx.x; t < 256 * 6; t += blockDim.x) {
        int k = t / 6, j = t % 6;
        float v;
        if (j < 2)      v = W2r1[k * 2 + j];
        else if (j < 4) v = W2r2[k * 2 + (j - 2)];
        else            v = mlp2_W[k * 2 + (j - 4)];
        Ws[t] = v;
    }
    __syncthreads();

    int warp = threadIdx.x >> 5, lane = threadIdx.x & 31;
    int row = blockIdx.x * 8 + warp;
    if (row >= M) return;

    float acc[6] = {0.f, 0.f, 0.f, 0.f, 0.f, 0.f};
    const float* xr = g_X1 + (size_t)row * 256;
    for (int k = lane; k < 256; k += 32) {
        float xv = xr[k];
#pragma unroll
        for (int j = 0; j < 6; j++) acc[j] = fmaf(xv, Ws[k * 6 + j], acc[j]);
    }
#pragma unroll
    for (int off = 16; off; off >>= 1)
#pragma unroll
        for (int j = 0; j < 6; j++) acc[j] += __shfl_xor_sync(0xffffffffu, acc[j], off);

    if (lane == 0) {
        float* z = g_Z2 + (size_t)row * 4;
        z[0] = acc[0]; z[1] = acc[1]; z[2] = acc[2]; z[3] = acc[3];
        out[row * 2 + 0] = b2r1[0] + b2r2[0] + tanhf(acc[4] + mlp2_b[0]);
        out[row * 2 + 1] = b2r1[1] + b2r2[1] + tanhf(acc[5] + mlp2_b[1]);
    }
}

// ---------------- layer-2 aggregation: warp-per-node gather, no atomics ----------------
__global__ __launch_bounds__(256)
void gather2_out(float* __restrict__ out, int M) {
    const int warp = threadIdx.x >> 5, lane = threadIdx.x & 31;
    const int i = blockIdx.x * 8 + warp;
    if (i >= M) return;

    float s0 = 0.f, s1 = 0.f;
    {
        const int n = min(g_cnt_adj[i], ECAP);
        const float2* eb = g_edge_adj + (size_t)i * ECAP;
        for (int e = lane; e < n; e += 32) {
            float2 ev = __ldg(eb + e);
            int c = __float_as_int(ev.x);
            float2 z = *reinterpret_cast<const float2*>(g_Z2 + (size_t)c * 4);
            s0 += ev.y * z.x;
            s1 += ev.y * z.y;
        }
    }
    {
        const int n = min(g_cnt_s[i], ECAP);
        const float2* eb = g_edge_s + (size_t)i * ECAP;
        for (int e = lane; e < n; e += 32) {
            float2 ev = __ldg(eb + e);
            int c = __float_as_int(ev.x);
            float2 z = *reinterpret_cast<const float2*>(g_Z2 + (size_t)c * 4 + 2);
            s0 += ev.y * z.x;
            s1 += ev.y * z.y;
        }
    }
#pragma unroll
    for (int off = 16; off; off >>= 1) {
        s0 += __shfl_xor_sync(0xffffffffu, s0, off);
        s1 += __shfl_xor_sync(0xffffffffu, s1, off);
    }
    if (lane == 0) {
        out[i * 2 + 0] += s0;
        out[i * 2 + 1] += s1;
    }
}

// ---------------- launch ----------------
extern "C" void kernel_launch(void* const* d_in, const int* in_sizes, int n_in,
                              void* d_out, int out_size) {
    const float* x        = (const float*)d_in[0];
    const int*   adj_rows = (const int*)d_in[1];
    const int*   adj_cols = (const int*)d_in[2];
    const float* adj_vals = (const float*)d_in[3];
    const int*   s_rows   = (const int*)d_in[4];
    const int*   s_cols   = (const int*)d_in[5];
    const float* s_vals   = (const float*)d_in[6];
    const float* W1r1     = (const float*)d_in[7];
    const float* b1r1     = (const float*)d_in[8];
    const float* W1r2     = (const float*)d_in[9];
    const float* b1r2     = (const float*)d_in[10];
    const float* mlp1_W   = (const float*)d_in[11];
    const float* mlp1_b   = (const float*)d_in[12];
    const float* af1_w    = (const float*)d_in[13];
    const float* W2r1     = (const float*)d_in[14];
    const float* b2r1     = (const float*)d_in[15];
    const float* W2r2     = (const float*)d_in[16];
    const float* b2r2     = (const float*)d_in[17];
    const float* mlp2_W   = (const float*)d_in[18];
    const float* mlp2_b   = (const float*)d_in[19];
    float* out = (float*)d_out;

    const int E = in_sizes[1];
    const int M = N_NODES;

    cudaFuncSetAttribute(gemm1_mma, cudaFuncAttributeMaxDynamicSharedMemorySize, GSMEM);

    // prep
    split_x_zero<<<1184, 256>>>(x);
    pack_w1split<<<(768 * 768 + 255) / 256, 256>>>(W1r1, W1r2, mlp1_W);
    build_buckets<<<(2 * E + 255) / 256, 256>>>(adj_rows, adj_cols, adj_vals,
                                                s_rows, s_cols, s_vals, E);

    // layer 1 big GEMM on tensor cores (HMMA fp16, 2 products)
    dim3 g1(6, (M + 127) / 128);
    gemm1_mma<<<g1, 256, GSMEM>>>(mlp1_b, M);

    // layer 1 aggregation + attention fusion (gather, no atomics)
    gather_att<<<M, 256>>>(b1r1, b1r2, af1_w);

    // layer 2
    gemm2_out<<<(M + 7) / 8, 256>>>(W2r1, W2r2, mlp2_W, b2r1, b2r2, mlp2_b, out, M);
    gather2_out<<<(M + 7) / 8, 256>>>(out, M);
}

// round 9
// speedup vs baseline: 2.4450x; 1.0547x over previous
#include <cuda_runtime.h>
#include <cuda_fp16.h>
#include <math.h>
#include <stdint.h>

#define N_NODES 50000
#define D_IN    768
#define NHID    256
#define ECAP    128                      // slots per row-bucket (P(overflow) ~ e^-49)

// ---------------- device scratch (no allocations allowed) ----------------
__device__ __half g_C1h[(size_t)N_NODES * 512];  // branch features (r1 cols 0..255, r2 256..511), fp16
__device__ float  g_C1m[(size_t)N_NODES * 256];  // tanh mlp branch, fp32
__device__ float  g_X1[(size_t)N_NODES * 256];   // fused layer-1 output
__device__ float  g_Z2[(size_t)N_NODES * 4];     // x1 @ [W2r1 | W2r2]

// fp16 operands for the tensor-core GEMM: x rounded to fp16, W split hi+lo
__device__ __half g_xh[(size_t)N_NODES * 768];
__device__ __half g_Whi[768 * 768];              // transposed: [n][k] = Wcat[k][n]
__device__ __half g_Wlo[768 * 768];

// bucketed-CSR edge storage: per destination row, up to ECAP (col,val) pairs
__device__ int    g_cnt_adj[N_NODES];
__device__ int    g_cnt_s[N_NODES];
__device__ float2 g_edge_adj[(size_t)N_NODES * ECAP];   // .x = col (int bits), .y = val
__device__ float2 g_edge_s[(size_t)N_NODES * ECAP];

// ================= helpers =================
__device__ __forceinline__ uint32_t smem_u32(const void* p) {
    uint32_t a;
    asm("{ .reg .u64 t; cvta.to.shared.u64 t, %1; cvt.u32.u64 %0, t; }" : "=r"(a) : "l"(p));
    return a;
}
__device__ __forceinline__ void cp16(uint32_t dst, const void* src) {
    asm volatile("cp.async.cg.shared.global [%0], [%1], 16;" :: "r"(dst), "l"(src));
}
__device__ __forceinline__ void ldsm_x4(uint32_t* r, uint32_t addr) {
    asm volatile("ldmatrix.sync.aligned.m8n8.x4.shared.b16 {%0,%1,%2,%3}, [%4];"
                 : "=r"(r[0]), "=r"(r[1]), "=r"(r[2]), "=r"(r[3]) : "r"(addr));
}
__device__ __forceinline__ void mma_f16(float* c, const uint32_t* a, const uint32_t* b) {
    asm volatile("mma.sync.aligned.m16n8k16.row.col.f32.f16.f16.f32 "
                 "{%0,%1,%2,%3}, {%4,%5,%6,%7}, {%8,%9}, {%0,%1,%2,%3};"
                 : "+f"(c[0]), "+f"(c[1]), "+f"(c[2]), "+f"(c[3])
                 : "r"(a[0]), "r"(a[1]), "r"(a[2]), "r"(a[3]), "r"(b[0]), "r"(b[1]));
}

// ---------------- prep: x -> fp16 AND zero edge counters ----------------
__global__ void split_x_zero(const float* __restrict__ x) {
    size_t stride = (size_t)gridDim.x * blockDim.x;
    size_t i = (size_t)blockIdx.x * blockDim.x + threadIdx.x;
    const size_t totalX = (size_t)N_NODES * 768;
    for (size_t j = i; j < totalX; j += stride)
        g_xh[j] = __float2half_rn(x[j]);
    for (size_t j = i; j < N_NODES; j += stride) {
        g_cnt_adj[j] = 0;
        g_cnt_s[j] = 0;
    }
}

// ---------------- prep: pack + transpose + fp16-split layer-1 weights ----------------
__global__ void pack_w1split(const float* __restrict__ W1r1,
                             const float* __restrict__ W1r2,
                             const float* __restrict__ mlp1_W) {
    int idx = blockIdx.x * blockDim.x + threadIdx.x;
    if (idx >= 768 * 768) return;
    int n = idx / 768, k = idx % 768;     // output [n][k] = W[k][n]
    float v;
    if (n < 256)       v = W1r1[k * 256 + n];
    else if (n < 512)  v = W1r2[k * 256 + (n - 256)];
    else               v = mlp1_W[k * 256 + (n - 512)];
    __half hi = __float2half_rn(v);
    g_Whi[idx] = hi;
    g_Wlo[idx] = __float2half_rn(v - __half2float(hi));
}

// ---------------- build row buckets for both edge sets ----------------
__global__ void build_buckets(const int* __restrict__ adj_rows,
                              const int* __restrict__ adj_cols,
                              const float* __restrict__ adj_vals,
                              const int* __restrict__ s_rows,
                              const int* __restrict__ s_cols,
                              const float* __restrict__ s_vals,
                              int E) {
    int idx = blockIdx.x * blockDim.x + threadIdx.x;
    if (idx < E) {
        int r = adj_rows[idx];
        int slot = atomicAdd(&g_cnt_adj[r], 1);
        if (slot < ECAP)
            g_edge_adj[(size_t)r * ECAP + slot] =
                make_float2(__int_as_float(adj_cols[idx]), adj_vals[idx]);
    } else if (idx < 2 * E) {
        int j = idx - E;
        int r = s_rows[j];
        int slot = atomicAdd(&g_cnt_s[r], 1);
        if (slot < ECAP)
            g_edge_s[(size_t)r * ECAP + slot] =
                make_float2(__int_as_float(s_cols[j]), s_vals[j]);
    }
}

// ================= GEMM1 via mma.sync (HMMA fp16, 2 products) =================
// [branch cols -> g_C1h as fp16 | mlp cols -> tanh -> g_C1m as fp32]
#define BKC 16
#define ROWB 48                         // padded row stride in bytes (24 fp16)
#define GTILE (128 * ROWB)              // 6144 B per operand tile
#define GSTAGE (3 * GTILE)              // A, Bhi, Blo = 18432 B
#define NSTAGE 4
#define GSMEM  (NSTAGE * GSTAGE)        // 73728 B (needs opt-in attribute)
#define NCHUNK (768 / BKC)              // 48

__global__ __launch_bounds__(256, 2)
void gemm1_mma(const float* __restrict__ mlp1_b, int M) {
    extern __shared__ char dsm[];
    const uint32_t base = smem_u32(dsm);

    const int tid = threadIdx.x;
    const int lane = tid & 31, wid = tid >> 5;
    const int warp_m = wid >> 2;
    const int warp_n = wid & 3;
    const int tileM = blockIdx.y * 128;
    const int nBase = blockIdx.x * 128;

    const int ldR = tid >> 1;
    const int ldG = tid & 1;
    int srcRowA = tileM + ldR; if (srcRowA >= M) srcRowA = M - 1;
    const uint32_t ldDst = ldR * ROWB + ldG * 16;
    const size_t aBase = (size_t)srcRowA * 768 + ldG * 8;
    const size_t bBase = (size_t)(nBase + ldR) * 768 + ldG * 8;

    const int aRow = warp_m * 64 + (lane & 15);
    const int aK   = (lane >> 4) * 8;
    uint32_t aOff[4];
#pragma unroll
    for (int mi = 0; mi < 4; mi++) aOff[mi] = (uint32_t)((aRow + mi * 16) * ROWB + aK * 2);
    const int bN = warp_n * 32 + (lane & 7) + ((lane >> 4) << 3);
    const int bK = ((lane >> 3) & 1) * 8;
    uint32_t bOff[2];
#pragma unroll
    for (int p = 0; p < 2; p++) bOff[p] = (uint32_t)((bN + p * 16) * ROWB + bK * 2);

    float acc[4][4][4];
#pragma unroll
    for (int mi = 0; mi < 4; mi++)
#pragma unroll
        for (int ni = 0; ni < 4; ni++)
#pragma unroll
            for (int r = 0; r < 4; r++) acc[mi][ni][r] = 0.f;

#pragma unroll
    for (int pc = 0; pc < 3; pc++) {
        uint32_t st = base + pc * GSTAGE;
        const size_t k0 = (size_t)pc * BKC;
        cp16(st + ldDst,             g_xh  + aBase + k0);
        cp16(st + GTILE + ldDst,     g_Whi + bBase + k0);
        cp16(st + 2 * GTILE + ldDst, g_Wlo + bBase + k0);
        asm volatile("cp.async.commit_group;" ::: "memory");
    }

    for (int kc = 0; kc < NCHUNK; ++kc) {
        if (kc + 2 < NCHUNK) {
            asm volatile("cp.async.wait_group 2;" ::: "memory");
        } else if (kc + 1 < NCHUNK) {
            asm volatile("cp.async.wait_group 1;" ::: "memory");
        } else {
            asm volatile("cp.async.wait_group 0;" ::: "memory");
        }
        __syncthreads();

        if (kc + 3 < NCHUNK) {
            uint32_t st = base + ((kc + 3) % NSTAGE) * GSTAGE;
            const size_t k0 = (size_t)(kc + 3) * BKC;
            cp16(st + ldDst,             g_xh  + aBase + k0);
            cp16(st + GTILE + ldDst,     g_Whi + bBase + k0);
            cp16(st + 2 * GTILE + ldDst, g_Wlo + bBase + k0);
            asm volatile("cp.async.commit_group;" ::: "memory");
        }

        const uint32_t stCur = base + (kc % NSTAGE) * GSTAGE;
        uint32_t bh[2][4], bl[2][4];
#pragma unroll
        for (int p = 0; p < 2; p++) {
            ldsm_x4(bh[p], stCur + GTILE + bOff[p]);
            ldsm_x4(bl[p], stCur + 2 * GTILE + bOff[p]);
        }
#pragma unroll
        for (int mi = 0; mi < 4; mi++) {
            uint32_t ah[4];
            ldsm_x4(ah, stCur + aOff[mi]);
#pragma unroll
            for (int ni = 0; ni < 4; ni++) {
                const int p = ni >> 1, h = (ni & 1) * 2;
                mma_f16(acc[mi][ni], ah, &bh[p][h]);
                mma_f16(acc[mi][ni], ah, &bl[p][h]);
            }
        }
    }

    // epilogue: branch tiles -> fp16 g_C1h; mlp tiles -> tanh fp32 g_C1m
    const bool isMlp = (nBase >= 512);
    const int rBase = tileM + warp_m * 64 + (lane >> 2);
    const int cBase = nBase + warp_n * 32 + 2 * (lane & 3);
#pragma unroll
    for (int mi = 0; mi < 4; mi++) {
#pragma unroll
        for (int half = 0; half < 2; half++) {
            const int row = rBase + mi * 16 + half * 8;
            if (row >= M) continue;
#pragma unroll
            for (int ni = 0; ni < 4; ni++) {
                const int col = cBase + ni * 8;
                float v0 = acc[mi][ni][half * 2 + 0];
                float v1 = acc[mi][ni][half * 2 + 1];
                if (isMlp) {
                    v0 = tanhf(v0 + mlp1_b[col - 512]);
                    v1 = tanhf(v1 + mlp1_b[col - 511]);
                    *reinterpret_cast<float2*>(g_C1m + (size_t)row * 256 + (col - 512)) =
                        make_float2(v0, v1);
                } else {
                    *reinterpret_cast<__half2*>(g_C1h + (size_t)row * 512 + col) =
                        __floats2half2_rn(v0, v1);
                }
            }
        }
    }
}

// ---------------- fused layer-1 aggregation: gather both branches + attention ----------------
__global__ __launch_bounds__(256)
void gather_att(const float* __restrict__ b1r1,
                const float* __restrict__ b1r2,
                const float* __restrict__ af) {
    const int i = blockIdx.x;
    const int h = threadIdx.x;
    const int lane = h & 31, warp = h >> 5;

    float v1 = 0.f;
    {
        const int n = min(g_cnt_adj[i], ECAP);
        const float2* eb = g_edge_adj + (size_t)i * ECAP;
        for (int e = 0; e < n; e++) {
            float2 ev = __ldg(eb + e);
            int c = __float_as_int(ev.x);
            v1 += ev.y * __half2float(__ldg(g_C1h + (size_t)c * 512 + h));
        }
        v1 += b1r1[h];
    }
    float v2 = 0.f;
    {
        const int n = min(g_cnt_s[i], ECAP);
        const float2* eb = g_edge_s + (size_t)i * ECAP;
        for (int e = 0; e < n; e++) {
            float2 ev = __ldg(eb + e);
            int c = __float_as_int(ev.x);
            v2 += ev.y * __half2float(__ldg(g_C1h + (size_t)c * 512 + 256 + h));
        }
        v2 += b1r2[h];
    }
    float v3 = g_C1m[(size_t)i * 256 + h];

    float p0 = v1 * af[h * 3 + 0] + v2 * af[(256 + h) * 3 + 0] + v3 * af[(512 + h) * 3 + 0];
    float p1 = v1 * af[h * 3 + 1] + v2 * af[(256 + h) * 3 + 1] + v3 * af[(512 + h) * 3 + 1];
    float p2 = v1 * af[h * 3 + 2] + v2 * af[(256 + h) * 3 + 2] + v3 * af[(512 + h) * 3 + 2];

#pragma unroll
    for (int off = 16; off; off >>= 1) {
        p0 += __shfl_xor_sync(0xffffffffu, p0, off);
        p1 += __shfl_xor_sync(0xffffffffu, p1, off);
        p2 += __shfl_xor_sync(0xffffffffu, p2, off);
    }
    __shared__ float red[8][3];
    if (lane == 0) { red[warp][0] = p0; red[warp][1] = p1; red[warp][2] = p2; }
    __syncthreads();

    float a0 = 0.f, a1 = 0.f, a2 = 0.f;
#pragma unroll
    for (int w = 0; w < 8; w++) { a0 += red[w][0]; a1 += red[w][1]; a2 += red[w][2]; }

    a0 = fabsf(a0); a1 = fabsf(a1); a2 = fabsf(a2);
    float m = fmaxf(a0, fmaxf(a1, a2));
    float e0 = __expf(a0 - m), e1 = __expf(a1 - m), e2 = __expf(a2 - m);
    float inv = 1.0f / (e0 + e1 + e2);

    g_X1[(size_t)i * 256 + h] = v1 * (e0 * inv) + v2 * (e1 * inv) + v3 * (e2 * inv);
}

// ---------------- GEMM2 fused: Z2 (r1,r2 cols) + out init ----------------
__global__ void gemm2_out(const float* __restrict__ W2r1,
                          const float* __restrict__ W2r2,
                          const float* __restrict__ mlp2_W,
                          const float* __restrict__ b2r1,
                          const float* __restrict__ b2r2,
                          const float* __restrict__ mlp2_b,
                          float* __restrict__ out, int M) {
    __shared__ float Ws[256 * 6];
    for (int t = threadIdx.x; t < 256 * 6; t += blockDim.x) {
        int k = t / 6, j = t % 6;
        float v;
        if (j < 2)      v = W2r1[k * 2 + j];
        else if (j < 4) v = W2r2[k * 2 + (j - 2)];
        else            v = mlp2_W[k * 2 + (j - 4)];
        Ws[t] = v;
    }
    __syncthreads();

    int warp = threadIdx.x >> 5, lane = threadIdx.x & 31;
    int row = blockIdx.x * 8 + warp;
    if (row >= M) return;

    float acc[6] = {0.f, 0.f, 0.f, 0.f, 0.f, 0.f};
    const float* xr = g_X1 + (size_t)row * 256;
    for (int k = lane; k < 256; k += 32) {
        float xv = xr[k];
#pragma unroll
        for (int j = 0; j < 6; j++) acc[j] = fmaf(xv, Ws[k * 6 + j], acc[j]);
    }
#pragma unroll
    for (int off = 16; off; off >>= 1)
#pragma unroll
        for (int j = 0; j < 6; j++) acc[j] += __shfl_xor_sync(0xffffffffu, acc[j], off);

    if (lane == 0) {
        float* z = g_Z2 + (size_t)row * 4;
        z[0] = acc[0]; z[1] = acc[1]; z[2] = acc[2]; z[3] = acc[3];
        out[row * 2 + 0] = b2r1[0] + b2r2[0] + tanhf(acc[4] + mlp2_b[0]);
        out[row * 2 + 1] = b2r1[1] + b2r2[1] + tanhf(acc[5] + mlp2_b[1]);
    }
}

// ---------------- layer-2 aggregation: warp-per-node gather, no atomics ----------------
__global__ __launch_bounds__(256)
void gather2_out(float* __restrict__ out, int M) {
    const int warp = threadIdx.x >> 5, lane = threadIdx.x & 31;
    const int i = blockIdx.x * 8 + warp;
    if (i >= M) return;

    float s0 = 0.f, s1 = 0.f;
    {
        const int n = min(g_cnt_adj[i], ECAP);
        const float2* eb = g_edge_adj + (size_t)i * ECAP;
        for (int e = lane; e < n; e += 32) {
            float2 ev = __ldg(eb + e);
            int c = __float_as_int(ev.x);
            float2 z = *reinterpret_cast<const float2*>(g_Z2 + (size_t)c * 4);
            s0 += ev.y * z.x;
            s1 += ev.y * z.y;
        }
    }
    {
        const int n = min(g_cnt_s[i], ECAP);
        const float2* eb = g_edge_s + (size_t)i * ECAP;
        for (int e = lane; e < n; e += 32) {
            float2 ev = __ldg(eb + e);
            int c = __float_as_int(ev.x);
            float2 z = *reinterpret_cast<const float2*>(g_Z2 + (size_t)c * 4 + 2);
            s0 += ev.y * z.x;
            s1 += ev.y * z.y;
        }
    }
#pragma unroll
    for (int off = 16; off; off >>= 1) {
        s0 += __shfl_xor_sync(0xffffffffu, s0, off);
        s1 += __shfl_xor_sync(0xffffffffu, s1, off);
    }
    if (lane == 0) {
        out[i * 2 + 0] += s0;
        out[i * 2 + 1] += s1;
    }
}

// ---------------- launch ----------------
extern "C" void kernel_launch(void* const* d_in, const int* in_sizes, int n_in,
                              void* d_out, int out_size) {
    const float* x        = (const float*)d_in[0];
    const int*   adj_rows = (const int*)d_in[1];
    const int*   adj_cols = (const int*)d_in[2];
    const float* adj_vals = (const float*)d_in[3];
    const int*   s_rows   = (const int*)d_in[4];
    const int*   s_cols   = (const int*)d_in[5];
    const float* s_vals   = (const float*)d_in[6];
    const float* W1r1     = (const float*)d_in[7];
    const float* b1r1     = (const float*)d_in[8];
    const float* W1r2     = (const float*)d_in[9];
    const float* b1r2     = (const float*)d_in[10];
    const float* mlp1_W   = (const float*)d_in[11];
    const float* mlp1_b   = (const float*)d_in[12];
    const float* af1_w    = (const float*)d_in[13];
    const float* W2r1     = (const float*)d_in[14];
    const float* b2r1     = (const float*)d_in[15];
    const float* W2r2     = (const float*)d_in[16];
    const float* b2r2     = (const float*)d_in[17];
    const float* mlp2_W   = (const float*)d_in[18];
    const float* mlp2_b   = (const float*)d_in[19];
    float* out = (float*)d_out;

    const int E = in_sizes[1];
    const int M = N_NODES;

    cudaFuncSetAttribute(gemm1_mma, cudaFuncAttributeMaxDynamicSharedMemorySize, GSMEM);

    // prep
    split_x_zero<<<1184, 256>>>(x);
    pack_w1split<<<(768 * 768 + 255) / 256, 256>>>(W1r1, W1r2, mlp1_W);
    build_buckets<<<(2 * E + 255) / 256, 256>>>(adj_rows, adj_cols, adj_vals,
                                                s_rows, s_cols, s_vals, E);

    // layer 1 big GEMM on tensor cores (HMMA fp16, 2 products)
    dim3 g1(6, (M + 127) / 128);
    gemm1_mma<<<g1, 256, GSMEM>>>(mlp1_b, M);

    // layer 1 aggregation + attention fusion (gather, no atomics)
    gather_att<<<M, 256>>>(b1r1, b1r2, af1_w);

    // layer 2
    gemm2_out<<<(M + 7) / 8, 256>>>(W2r1, W2r2, mlp2_W, b2r1, b2r2, mlp2_b, out, M);
    gather2_out<<<(M + 7) / 8, 256>>>(out, M);
}

// round 10
// speedup vs baseline: 2.9166x; 1.1929x over previous
#include <cuda_runtime.h>
#include <cuda_fp16.h>
#include <math.h>
#include <stdint.h>

#define N_NODES 50000
#define D_IN    768
#define NHID    256
#define ECAP    128                      // slots per row-bucket (P(overflow) ~ e^-49)

// ---------------- device scratch (no allocations allowed) ----------------
__device__ __half g_C1h[(size_t)N_NODES * 512];  // branch features (r1 0..255, r2 256..511), fp16
__device__ float  g_C1m[(size_t)N_NODES * 256];  // tanh mlp branch, fp32
__device__ float  g_X1[(size_t)N_NODES * 256];   // fused layer-1 output
__device__ float  g_Z2[(size_t)N_NODES * 4];     // x1 @ [W2r1 | W2r2]

// fp16 operands for the tensor-core GEMM: x rounded to fp16, W split hi+lo
__device__ __half g_xh[(size_t)N_NODES * 768];
__device__ __half g_Whi[768 * 768];              // transposed: [n][k] = Wcat[k][n]
__device__ __half g_Wlo[768 * 768];

// bucketed-CSR edge storage
__device__ int    g_cnt_adj[N_NODES];
__device__ int    g_cnt_s[N_NODES];
__device__ float2 g_edge_adj[(size_t)N_NODES * ECAP];   // .x = col (int bits), .y = val
__device__ float2 g_edge_s[(size_t)N_NODES * ECAP];

// ================= helpers =================
__device__ __forceinline__ uint32_t smem_u32(const void* p) {
    uint32_t a;
    asm("{ .reg .u64 t; cvta.to.shared.u64 t, %1; cvt.u32.u64 %0, t; }" : "=r"(a) : "l"(p));
    return a;
}
__device__ __forceinline__ void cp16(uint32_t dst, const void* src) {
    asm volatile("cp.async.cg.shared.global [%0], [%1], 16;" :: "r"(dst), "l"(src));
}
__device__ __forceinline__ void ldsm_x4(uint32_t* r, uint32_t addr) {
    asm volatile("ldmatrix.sync.aligned.m8n8.x4.shared.b16 {%0,%1,%2,%3}, [%4];"
                 : "=r"(r[0]), "=r"(r[1]), "=r"(r[2]), "=r"(r[3]) : "r"(addr));
}
__device__ __forceinline__ void mma_f16(float* c, const uint32_t* a, const uint32_t* b) {
    asm volatile("mma.sync.aligned.m16n8k16.row.col.f32.f16.f16.f32 "
                 "{%0,%1,%2,%3}, {%4,%5,%6,%7}, {%8,%9}, {%0,%1,%2,%3};"
                 : "+f"(c[0]), "+f"(c[1]), "+f"(c[2]), "+f"(c[3])
                 : "r"(a[0]), "r"(a[1]), "r"(a[2]), "r"(a[3]), "r"(b[0]), "r"(b[1]));
}

// ---------------- prep: x -> fp16 (vectorized) AND zero edge counters ----------------
__global__ void split_x_zero(const float* __restrict__ x) {
    size_t stride = (size_t)gridDim.x * blockDim.x;
    size_t i = (size_t)blockIdx.x * blockDim.x + threadIdx.x;
    const size_t total4 = (size_t)N_NODES * 768 / 4;
    const float4* x4 = reinterpret_cast<const float4*>(x);
    __half2* out2 = reinterpret_cast<__half2*>(g_xh);
    for (size_t j = i; j < total4; j += stride) {
        float4 v = x4[j];
        out2[2 * j + 0] = __floats2half2_rn(v.x, v.y);
        out2[2 * j + 1] = __floats2half2_rn(v.z, v.w);
    }
    for (size_t j = i; j < N_NODES; j += stride) {
        g_cnt_adj[j] = 0;
        g_cnt_s[j] = 0;
    }
}

// ---------------- prep: pack + transpose + fp16-split layer-1 weights ----------------
__global__ void pack_w1split(const float* __restrict__ W1r1,
                             const float* __restrict__ W1r2,
                             const float* __restrict__ mlp1_W) {
    int idx = blockIdx.x * blockDim.x + threadIdx.x;
    if (idx >= 768 * 768) return;
    int n = idx / 768, k = idx % 768;     // output [n][k] = W[k][n]
    float v;
    if (n < 256)       v = W1r1[k * 256 + n];
    else if (n < 512)  v = W1r2[k * 256 + (n - 256)];
    else               v = mlp1_W[k * 256 + (n - 512)];
    __half hi = __float2half_rn(v);
    g_Whi[idx] = hi;
    g_Wlo[idx] = __float2half_rn(v - __half2float(hi));
}

// ---------------- build row buckets for both edge sets ----------------
__global__ void build_buckets(const int* __restrict__ adj_rows,
                              const int* __restrict__ adj_cols,
                              const float* __restrict__ adj_vals,
                              const int* __restrict__ s_rows,
                              const int* __restrict__ s_cols,
                              const float* __restrict__ s_vals,
                              int E) {
    int idx = blockIdx.x * blockDim.x + threadIdx.x;
    if (idx < E) {
        int r = adj_rows[idx];
        int slot = atomicAdd(&g_cnt_adj[r], 1);
        if (slot < ECAP)
            g_edge_adj[(size_t)r * ECAP + slot] =
                make_float2(__int_as_float(adj_cols[idx]), adj_vals[idx]);
    } else if (idx < 2 * E) {
        int j = idx - E;
        int r = s_rows[j];
        int slot = atomicAdd(&g_cnt_s[r], 1);
        if (slot < ECAP)
            g_edge_s[(size_t)r * ECAP + slot] =
                make_float2(__int_as_float(s_cols[j]), s_vals[j]);
    }
}

// ================= GEMM1 via mma.sync (HMMA fp16, 2 products, BK=32) =================
#define BKC 32
#define ROWB 80                         // 64B data + 16B pad (16B-aligned, conflict-free)
#define GTILE (128 * ROWB)              // 10240 B per operand tile
#define GSTAGE (3 * GTILE)              // A, Bhi, Blo = 30720 B
#define NSTAGE 3
#define GSMEM  (NSTAGE * GSTAGE)        // 92160 B (2 CTA/SM: 184 KB <= 228 KB)
#define NCHUNK (768 / BKC)              // 24

__global__ __launch_bounds__(256, 2)
void gemm1_mma(const float* __restrict__ mlp1_b, int M) {
    extern __shared__ char dsm[];
    const uint32_t base = smem_u32(dsm);

    const int tid = threadIdx.x;
    const int lane = tid & 31, wid = tid >> 5;
    const int warp_m = wid >> 2;          // 0..1
    const int warp_n = wid & 3;           // 0..3
    const int tileM = blockIdx.y * 128;
    const int nBase = blockIdx.x * 128;

    // loader: thread t covers rows (t>>2) and (t>>2)+64, 16B chunk (t&3) of the 64B row
    const int ldRow = tid >> 2;
    const int ldC = tid & 3;
    int rA0 = tileM + ldRow;      if (rA0 >= M) rA0 = M - 1;
    int rA1 = tileM + ldRow + 64; if (rA1 >= M) rA1 = M - 1;
    const uint32_t ldDst0 = ldRow * ROWB + ldC * 16;
    const uint32_t ldDst1 = (ldRow + 64) * ROWB + ldC * 16;
    const size_t aBase0 = (size_t)rA0 * 768 + ldC * 8;
    const size_t aBase1 = (size_t)rA1 * 768 + ldC * 8;
    const size_t bBase0 = (size_t)(nBase + ldRow) * 768 + ldC * 8;
    const size_t bBase1 = (size_t)(nBase + ldRow + 64) * 768 + ldC * 8;

    // ldmatrix per-thread offsets (byte offset within a k-step selected by +ks*32)
    const int aRow = warp_m * 64 + (lane & 15);
    const uint32_t aSel = (uint32_t)((lane >> 4) * 16);
    uint32_t aOffB[4];
#pragma unroll
    for (int mi = 0; mi < 4; mi++) aOffB[mi] = (uint32_t)((aRow + mi * 16) * ROWB) + aSel;
    const int bN = warp_n * 32 + (lane & 7) + ((lane >> 4) << 3);
    const uint32_t bSel = (uint32_t)(((lane >> 3) & 1) * 16);
    uint32_t bOffB[2];
#pragma unroll
    for (int p = 0; p < 2; p++) bOffB[p] = (uint32_t)((bN + p * 16) * ROWB) + bSel;

    float acc[4][4][4];
#pragma unroll
    for (int mi = 0; mi < 4; mi++)
#pragma unroll
        for (int ni = 0; ni < 4; ni++)
#pragma unroll
            for (int r = 0; r < 4; r++) acc[mi][ni][r] = 0.f;

    // prologue: chunks 0,1 -> stages 0,1
#pragma unroll
    for (int pc = 0; pc < 2; pc++) {
        uint32_t st = base + pc * GSTAGE;
        const size_t k0 = (size_t)pc * BKC;
        cp16(st + ldDst0,             g_xh  + aBase0 + k0);
        cp16(st + ldDst1,             g_xh  + aBase1 + k0);
        cp16(st + GTILE + ldDst0,     g_Whi + bBase0 + k0);
        cp16(st + GTILE + ldDst1,     g_Whi + bBase1 + k0);
        cp16(st + 2 * GTILE + ldDst0, g_Wlo + bBase0 + k0);
        cp16(st + 2 * GTILE + ldDst1, g_Wlo + bBase1 + k0);
        asm volatile("cp.async.commit_group;" ::: "memory");
    }

    for (int kc = 0; kc < NCHUNK; ++kc) {
        if (kc + 1 < NCHUNK) {
            asm volatile("cp.async.wait_group 1;" ::: "memory");
        } else {
            asm volatile("cp.async.wait_group 0;" ::: "memory");
        }
        // Single barrier: chunk kc visible; all warps done with chunk kc-1,
        // whose stage (kc-1)%3 == (kc+2)%3 is overwritten below.
        __syncthreads();

        if (kc + 2 < NCHUNK) {
            uint32_t st = base + ((kc + 2) % NSTAGE) * GSTAGE;
            const size_t k0 = (size_t)(kc + 2) * BKC;
            cp16(st + ldDst0,             g_xh  + aBase0 + k0);
            cp16(st + ldDst1,             g_xh  + aBase1 + k0);
            cp16(st + GTILE + ldDst0,     g_Whi + bBase0 + k0);
            cp16(st + GTILE + ldDst1,     g_Whi + bBase1 + k0);
            cp16(st + 2 * GTILE + ldDst0, g_Wlo + bBase0 + k0);
            cp16(st + 2 * GTILE + ldDst1, g_Wlo + bBase1 + k0);
            asm volatile("cp.async.commit_group;" ::: "memory");
        }

        const uint32_t stCur = base + (kc % NSTAGE) * GSTAGE;
#pragma unroll
        for (int ks = 0; ks < 2; ks++) {
            const uint32_t ko = ks * 32;
            uint32_t bh[2][4], bl[2][4];
#pragma unroll
            for (int p = 0; p < 2; p++) {
                ldsm_x4(bh[p], stCur + GTILE + bOffB[p] + ko);
                ldsm_x4(bl[p], stCur + 2 * GTILE + bOffB[p] + ko);
            }
#pragma unroll
            for (int mi = 0; mi < 4; mi++) {
                uint32_t ah[4];
                ldsm_x4(ah, stCur + aOffB[mi] + ko);
#pragma unroll
                for (int ni = 0; ni < 4; ni++) {
                    const int p = ni >> 1, h = (ni & 1) * 2;
                    mma_f16(acc[mi][ni], ah, &bh[p][h]);
                    mma_f16(acc[mi][ni], ah, &bl[p][h]);
                }
            }
        }
    }

    // epilogue: branch tiles -> fp16 g_C1h; mlp tiles -> tanh fp32 g_C1m
    const bool isMlp = (nBase >= 512);
    const int rBase = tileM + warp_m * 64 + (lane >> 2);
    const int cBase = nBase + warp_n * 32 + 2 * (lane & 3);
#pragma unroll
    for (int mi = 0; mi < 4; mi++) {
#pragma unroll
        for (int half = 0; half < 2; half++) {
            const int row = rBase + mi * 16 + half * 8;
            if (row >= M) continue;
#pragma unroll
            for (int ni = 0; ni < 4; ni++) {
                const int col = cBase + ni * 8;
                float v0 = acc[mi][ni][half * 2 + 0];
                float v1 = acc[mi][ni][half * 2 + 1];
                if (isMlp) {
                    v0 = tanhf(v0 + mlp1_b[col - 512]);
                    v1 = tanhf(v1 + mlp1_b[col - 511]);
                    *reinterpret_cast<float2*>(g_C1m + (size_t)row * 256 + (col - 512)) =
                        make_float2(v0, v1);
                } else {
                    *reinterpret_cast<__half2*>(g_C1h + (size_t)row * 512 + col) =
                        __floats2half2_rn(v0, v1);
                }
            }
        }
    }
}

// ---------------- fused layer-1 aggregation v2: branch-parallel half2 gather ----------------
// 256 threads/node: t<128 gathers v1 (units 2t,2t+1), t>=128 gathers v2.
__global__ __launch_bounds__(256)
void gather_att(const float* __restrict__ b1r1,
                const float* __restrict__ b1r2,
                const float* __restrict__ af) {
    const int i = blockIdx.x;
    const int t = threadIdx.x;
    const int lane = t & 31, warp = t >> 5;
    const int br = t >> 7;                // 0: adj/v1, 1: s/v2
    const int u = (t & 127) * 2;          // first of 2 hidden units

    __shared__ float sv[768];             // v1[0..255], v2[256..511], v3[512..767]
    __shared__ float red[8][3];

    // gather 2 units via half2
    float s0 = 0.f, s1 = 0.f;
    {
        const int n = min(br ? g_cnt_s[i] : g_cnt_adj[i], ECAP);
        const float2* eb = (br ? g_edge_s : g_edge_adj) + (size_t)i * ECAP;
        const size_t colOff = (size_t)(br * 256 + u);
        for (int e = 0; e < n; e++) {
            float2 ev = __ldg(eb + e);
            int c = __float_as_int(ev.x);
            __half2 hv = __ldg(reinterpret_cast<const __half2*>(
                                   g_C1h + (size_t)c * 512 + colOff));
            float2 f = __half22float2(hv);
            s0 += ev.y * f.x;
            s1 += ev.y * f.y;
        }
        const float* bias = br ? b1r2 : b1r1;
        s0 += bias[u]; s1 += bias[u + 1];
    }
    // br==0 threads also fetch their v3 pair
    float t0 = 0.f, t1 = 0.f;
    if (br == 0) {
        float2 v3p = *reinterpret_cast<const float2*>(g_C1m + (size_t)i * 256 + u);
        t0 = v3p.x; t1 = v3p.y;
        sv[512 + u] = t0; sv[513 + u] = t1;
    }
    sv[br * 256 + u] = s0;
    sv[br * 256 + u + 1] = s1;

    // partial attention logits
    const int r0 = br * 256 + u;
    float p0 = s0 * af[r0 * 3 + 0] + s1 * af[(r0 + 1) * 3 + 0];
    float p1 = s0 * af[r0 * 3 + 1] + s1 * af[(r0 + 1) * 3 + 1];
    float p2 = s0 * af[r0 * 3 + 2] + s1 * af[(r0 + 1) * 3 + 2];
    if (br == 0) {
        const int r3 = 512 + u;
        p0 += t0 * af[r3 * 3 + 0] + t1 * af[(r3 + 1) * 3 + 0];
        p1 += t0 * af[r3 * 3 + 1] + t1 * af[(r3 + 1) * 3 + 1];
        p2 += t0 * af[r3 * 3 + 2] + t1 * af[(r3 + 1) * 3 + 2];
    }

#pragma unroll
    for (int off = 16; off; off >>= 1) {
        p0 += __shfl_xor_sync(0xffffffffu, p0, off);
        p1 += __shfl_xor_sync(0xffffffffu, p1, off);
        p2 += __shfl_xor_sync(0xffffffffu, p2, off);
    }
    if (lane == 0) { red[warp][0] = p0; red[warp][1] = p1; red[warp][2] = p2; }
    __syncthreads();

    float a0 = 0.f, a1 = 0.f, a2 = 0.f;
#pragma unroll
    for (int w = 0; w < 8; w++) { a0 += red[w][0]; a1 += red[w][1]; a2 += red[w][2]; }

    a0 = fabsf(a0); a1 = fabsf(a1); a2 = fabsf(a2);
    float m = fmaxf(a0, fmaxf(a1, a2));
    float e0 = __expf(a0 - m), e1 = __expf(a1 - m), e2 = __expf(a2 - m);
    float inv = 1.0f / (e0 + e1 + e2);
    float w0 = e0 * inv, w1 = e1 * inv, w2 = e2 * inv;

    // output: thread t writes hidden unit t
    g_X1[(size_t)i * 256 + t] = sv[t] * w0 + sv[256 + t] * w1 + sv[512 + t] * w2;
}

// ---------------- GEMM2 fused: Z2 (r1,r2 cols) + out init ----------------
__global__ void gemm2_out(const float* __restrict__ W2r1,
                          const float* __restrict__ W2r2,
                          const float* __restrict__ mlp2_W,
                          const float* __restrict__ b2r1,
                          const float* __restrict__ b2r2,
                          const float* __restrict__ mlp2_b,
                          float* __restrict__ out, int M) {
    __shared__ float Ws[256 * 6];
    for (int t = threadIdx.x; t < 256 * 6; t += blockDim.x) {
        int k = t / 6, j = t % 6;
        float v;
        if (j < 2)      v = W2r1[k * 2 + j];
        else if (j < 4) v = W2r2[k * 2 + (j - 2)];
        else            v = mlp2_W[k * 2 + (j - 4)];
        Ws[t] = v;
    }
    __syncthreads();

    int warp = threadIdx.x >> 5, lane = threadIdx.x & 31;
    int row = blockIdx.x * 8 + warp;
    if (row >= M) return;

    float acc[6] = {0.f, 0.f, 0.f, 0.f, 0.f, 0.f};
    const float* xr = g_X1 + (size_t)row * 256;
    for (int k = lane; k < 256; k += 32) {
        float xv = xr[k];
#pragma unroll
        for (int j = 0; j < 6; j++) acc[j] = fmaf(xv, Ws[k * 6 + j], acc[j]);
    }
#pragma unroll
    for (int off = 16; off; off >>= 1)
#pragma unroll
        for (int j = 0; j < 6; j++) acc[j] += __shfl_xor_sync(0xffffffffu, acc[j], off);

    if (lane == 0) {
        float* z = g_Z2 + (size_t)row * 4;
        z[0] = acc[0]; z[1] = acc[1]; z[2] = acc[2]; z[3] = acc[3];
        out[row * 2 + 0] = b2r1[0] + b2r2[0] + tanhf(acc[4] + mlp2_b[0]);
        out[row * 2 + 1] = b2r1[1] + b2r2[1] + tanhf(acc[5] + mlp2_b[1]);
    }
}

// ---------------- layer-2 aggregation: warp-per-node gather, no atomics ----------------
__global__ __launch_bounds__(256)
void gather2_out(float* __restrict__ out, int M) {
    const int warp = threadIdx.x >> 5, lane = threadIdx.x & 31;
    const int i = blockIdx.x * 8 + warp;
    if (i >= M) return;

    float s0 = 0.f, s1 = 0.f;
    {
        const int n = min(g_cnt_adj[i], ECAP);
        const float2* eb = g_edge_adj + (size_t)i * ECAP;
        for (int e = lane; e < n; e += 32) {
            float2 ev = __ldg(eb + e);
            int c = __float_as_int(ev.x);
            float2 z = *reinterpret_cast<const float2*>(g_Z2 + (size_t)c * 4);
            s0 += ev.y * z.x;
            s1 += ev.y * z.y;
        }
    }
    {
        const int n = min(g_cnt_s[i], ECAP);
        const float2* eb = g_edge_s + (size_t)i * ECAP;
        for (int e = lane; e < n; e += 32) {
            float2 ev = __ldg(eb + e);
            int c = __float_as_int(ev.x);
            float2 z = *reinterpret_cast<const float2*>(g_Z2 + (size_t)c * 4 + 2);
            s0 += ev.y * z.x;
            s1 += ev.y * z.y;
        }
    }
#pragma unroll
    for (int off = 16; off; off >>= 1) {
        s0 += __shfl_xor_sync(0xffffffffu, s0, off);
        s1 += __shfl_xor_sync(0xffffffffu, s1, off);
    }
    if (lane == 0) {
        out[i * 2 + 0] += s0;
        out[i * 2 + 1] += s1;
    }
}

// ---------------- launch ----------------
extern "C" void kernel_launch(void* const* d_in, const int* in_sizes, int n_in,
                              void* d_out, int out_size) {
    const float* x        = (const float*)d_in[0];
    const int*   adj_rows = (const int*)d_in[1];
    const int*   adj_cols = (const int*)d_in[2];
    const float* adj_vals = (const float*)d_in[3];
    const int*   s_rows   = (const int*)d_in[4];
    const int*   s_cols   = (const int*)d_in[5];
    const float* s_vals   = (const float*)d_in[6];
    const float* W1r1     = (const float*)d_in[7];
    const float* b1r1     = (const float*)d_in[8];
    const float* W1r2     = (const float*)d_in[9];
    const float* b1r2     = (const float*)d_in[10];
    const float* mlp1_W   = (const float*)d_in[11];
    const float* mlp1_b   = (const float*)d_in[12];
    const float* af1_w    = (const float*)d_in[13];
    const float* W2r1     = (const float*)d_in[14];
    const float* b2r1     = (const float*)d_in[15];
    const float* W2r2     = (const float*)d_in[16];
    const float* b2r2     = (const float*)d_in[17];
    const float* mlp2_W   = (const float*)d_in[18];
    const float* mlp2_b   = (const float*)d_in[19];
    float* out = (float*)d_out;

    const int E = in_sizes[1];
    const int M = N_NODES;

    cudaFuncSetAttribute(gemm1_mma, cudaFuncAttributeMaxDynamicSharedMemorySize, GSMEM);

    // prep
    split_x_zero<<<1184, 256>>>(x);
    pack_w1split<<<(768 * 768 + 255) / 256, 256>>>(W1r1, W1r2, mlp1_W);
    build_buckets<<<(2 * E + 255) / 256, 256>>>(adj_rows, adj_cols, adj_vals,
                                                s_rows, s_cols, s_vals, E);

    // layer 1 big GEMM on tensor cores (HMMA fp16, BK=32)
    dim3 g1(6, (M + 127) / 128);
    gemm1_mma<<<g1, 256, GSMEM>>>(mlp1_b, M);

    // layer 1 aggregation + attention fusion (branch-parallel half2 gather)
    gather_att<<<M, 256>>>(b1r1, b1r2, af1_w);

    // layer 2
    gemm2_out<<<(M + 7) / 8, 256>>>(W2r1, W2r2, mlp2_W, b2r1, b2r2, mlp2_b, out, M);
    gather2_out<<<(M + 7) / 8, 256>>>(out, M);
}

// round 11
// speedup vs baseline: 3.5349x; 1.2120x over previous
#include <cuda_runtime.h>
#include <cuda_fp16.h>
#include <math.h>
#include <stdint.h>

#define N_NODES 50000
#define D_IN    768
#define NHID    256
#define ECAP    128                      // slots per row-bucket (P(overflow) ~ e^-49)

// ---------------- device scratch (no allocations allowed) ----------------
__device__ __half g_C1h[(size_t)N_NODES * 512];  // branch features (r1 0..255, r2 256..511), fp16
__device__ float  g_C1m[(size_t)N_NODES * 256];  // tanh mlp branch, fp32
__device__ float  g_X1[(size_t)N_NODES * 256];   // fused layer-1 output
__device__ float  g_Z2[(size_t)N_NODES * 4];     // x1 @ [W2r1 | W2r2]

// fp16 operands for the tensor-core GEMM (both rounded to fp16)
__device__ __half g_xh[(size_t)N_NODES * 768];
__device__ __half g_Whi[768 * 768];              // transposed: [n][k] = Wcat[k][n]

// bucketed-CSR edge storage
__device__ int    g_cnt_adj[N_NODES];
__device__ int    g_cnt_s[N_NODES];
__device__ float2 g_edge_adj[(size_t)N_NODES * ECAP];   // .x = col (int bits), .y = val
__device__ float2 g_edge_s[(size_t)N_NODES * ECAP];

// ================= helpers =================
__device__ __forceinline__ uint32_t smem_u32(const void* p) {
    uint32_t a;
    asm("{ .reg .u64 t; cvta.to.shared.u64 t, %1; cvt.u32.u64 %0, t; }" : "=r"(a) : "l"(p));
    return a;
}
__device__ __forceinline__ void cp16(uint32_t dst, const void* src) {
    asm volatile("cp.async.cg.shared.global [%0], [%1], 16;" :: "r"(dst), "l"(src));
}
__device__ __forceinline__ void ldsm_x4(uint32_t* r, uint32_t addr) {
    asm volatile("ldmatrix.sync.aligned.m8n8.x4.shared.b16 {%0,%1,%2,%3}, [%4];"
                 : "=r"(r[0]), "=r"(r[1]), "=r"(r[2]), "=r"(r[3]) : "r"(addr));
}
__device__ __forceinline__ void mma_f16(float* c, const uint32_t* a, const uint32_t* b) {
    asm volatile("mma.sync.aligned.m16n8k16.row.col.f32.f16.f16.f32 "
                 "{%0,%1,%2,%3}, {%4,%5,%6,%7}, {%8,%9}, {%0,%1,%2,%3};"
                 : "+f"(c[0]), "+f"(c[1]), "+f"(c[2]), "+f"(c[3])
                 : "r"(a[0]), "r"(a[1]), "r"(a[2]), "r"(a[3]), "r"(b[0]), "r"(b[1]));
}

// ---------------- prep: x -> fp16 (vectorized) AND zero edge counters ----------------
__global__ void split_x_zero(const float* __restrict__ x) {
    size_t stride = (size_t)gridDim.x * blockDim.x;
    size_t i = (size_t)blockIdx.x * blockDim.x + threadIdx.x;
    const size_t total4 = (size_t)N_NODES * 768 / 4;
    const float4* x4 = reinterpret_cast<const float4*>(x);
    __half2* out2 = reinterpret_cast<__half2*>(g_xh);
    for (size_t j = i; j < total4; j += stride) {
        float4 v = x4[j];
        out2[2 * j + 0] = __floats2half2_rn(v.x, v.y);
        out2[2 * j + 1] = __floats2half2_rn(v.z, v.w);
    }
    for (size_t j = i; j < N_NODES; j += stride) {
        g_cnt_adj[j] = 0;
        g_cnt_s[j] = 0;
    }
}

// ---------------- prep: pack + transpose layer-1 weights to fp16 ----------------
__global__ void pack_w1(const float* __restrict__ W1r1,
                        const float* __restrict__ W1r2,
                        const float* __restrict__ mlp1_W) {
    int idx = blockIdx.x * blockDim.x + threadIdx.x;
    if (idx >= 768 * 768) return;
    int n = idx / 768, k = idx % 768;     // output [n][k] = W[k][n]
    float v;
    if (n < 256)       v = W1r1[k * 256 + n];
    else if (n < 512)  v = W1r2[k * 256 + (n - 256)];
    else               v = mlp1_W[k * 256 + (n - 512)];
    g_Whi[idx] = __float2half_rn(v);
}

// ---------------- build row buckets for both edge sets ----------------
__global__ void build_buckets(const int* __restrict__ adj_rows,
                              const int* __restrict__ adj_cols,
                              const float* __restrict__ adj_vals,
                              const int* __restrict__ s_rows,
                              const int* __restrict__ s_cols,
                              const float* __restrict__ s_vals,
                              int E) {
    int idx = blockIdx.x * blockDim.x + threadIdx.x;
    if (idx < E) {
        int r = adj_rows[idx];
        int slot = atomicAdd(&g_cnt_adj[r], 1);
        if (slot < ECAP)
            g_edge_adj[(size_t)r * ECAP + slot] =
                make_float2(__int_as_float(adj_cols[idx]), adj_vals[idx]);
    } else if (idx < 2 * E) {
        int j = idx - E;
        int r = s_rows[j];
        int slot = atomicAdd(&g_cnt_s[r], 1);
        if (slot < ECAP)
            g_edge_s[(size_t)r * ECAP + slot] =
                make_float2(__int_as_float(s_cols[j]), s_vals[j]);
    }
}

// ================= GEMM1 via mma.sync (HMMA fp16, SINGLE product, BK=32) =================
#define BKC 32
#define ROWB 80                         // 64B data + 16B pad
#define GTILE (128 * ROWB)              // 10240 B per operand tile
#define GSTAGE (2 * GTILE)              // A, Whi = 20480 B
#define NSTAGE 4
#define GSMEM  (NSTAGE * GSTAGE)        // 81920 B (2 CTA/SM: 160 KB <= 228 KB)
#define NCHUNK (768 / BKC)              // 24

__global__ __launch_bounds__(256, 2)
void gemm1_mma(const float* __restrict__ mlp1_b, int M) {
    extern __shared__ char dsm[];
    const uint32_t base = smem_u32(dsm);

    const int tid = threadIdx.x;
    const int lane = tid & 31, wid = tid >> 5;
    const int warp_m = wid >> 2;          // 0..1
    const int warp_n = wid & 3;           // 0..3
    const int tileM = blockIdx.y * 128;
    const int nBase = blockIdx.x * 128;

    // loader: thread t covers rows (t>>2) and (t>>2)+64, 16B chunk (t&3) of the 64B row
    const int ldRow = tid >> 2;
    const int ldC = tid & 3;
    int rA0 = tileM + ldRow;      if (rA0 >= M) rA0 = M - 1;
    int rA1 = tileM + ldRow + 64; if (rA1 >= M) rA1 = M - 1;
    const uint32_t ldDst0 = ldRow * ROWB + ldC * 16;
    const uint32_t ldDst1 = (ldRow + 64) * ROWB + ldC * 16;
    const size_t aBase0 = (size_t)rA0 * 768 + ldC * 8;
    const size_t aBase1 = (size_t)rA1 * 768 + ldC * 8;
    const size_t bBase0 = (size_t)(nBase + ldRow) * 768 + ldC * 8;
    const size_t bBase1 = (size_t)(nBase + ldRow + 64) * 768 + ldC * 8;

    // ldmatrix per-thread offsets (k-step selected by +ks*32 bytes)
    const int aRow = warp_m * 64 + (lane & 15);
    const uint32_t aSel = (uint32_t)((lane >> 4) * 16);
    uint32_t aOffB[4];
#pragma unroll
    for (int mi = 0; mi < 4; mi++) aOffB[mi] = (uint32_t)((aRow + mi * 16) * ROWB) + aSel;
    const int bN = warp_n * 32 + (lane & 7) + ((lane >> 4) << 3);
    const uint32_t bSel = (uint32_t)(((lane >> 3) & 1) * 16);
    uint32_t bOffB[2];
#pragma unroll
    for (int p = 0; p < 2; p++) bOffB[p] = (uint32_t)((bN + p * 16) * ROWB) + bSel;

    float acc[4][4][4];
#pragma unroll
    for (int mi = 0; mi < 4; mi++)
#pragma unroll
        for (int ni = 0; ni < 4; ni++)
#pragma unroll
            for (int r = 0; r < 4; r++) acc[mi][ni][r] = 0.f;

    // prologue: chunks 0,1,2 -> stages 0,1,2
#pragma unroll
    for (int pc = 0; pc < 3; pc++) {
        uint32_t st = base + pc * GSTAGE;
        const size_t k0 = (size_t)pc * BKC;
        cp16(st + ldDst0,         g_xh  + aBase0 + k0);
        cp16(st + ldDst1,         g_xh  + aBase1 + k0);
        cp16(st + GTILE + ldDst0, g_Whi + bBase0 + k0);
        cp16(st + GTILE + ldDst1, g_Whi + bBase1 + k0);
        asm volatile("cp.async.commit_group;" ::: "memory");
    }

    for (int kc = 0; kc < NCHUNK; ++kc) {
        if (kc + 2 < NCHUNK) {
            asm volatile("cp.async.wait_group 2;" ::: "memory");
        } else if (kc + 1 < NCHUNK) {
            asm volatile("cp.async.wait_group 1;" ::: "memory");
        } else {
            asm volatile("cp.async.wait_group 0;" ::: "memory");
        }
        // Single barrier: chunk kc visible; all warps done with chunk kc-1,
        // whose stage (kc-1)%4 == (kc+3)%4 is overwritten below.
        __syncthreads();

        if (kc + 3 < NCHUNK) {
            uint32_t st = base + ((kc + 3) % NSTAGE) * GSTAGE;
            const size_t k0 = (size_t)(kc + 3) * BKC;
            cp16(st + ldDst0,         g_xh  + aBase0 + k0);
            cp16(st + ldDst1,         g_xh  + aBase1 + k0);
            cp16(st + GTILE + ldDst0, g_Whi + bBase0 + k0);
            cp16(st + GTILE + ldDst1, g_Whi + bBase1 + k0);
            asm volatile("cp.async.commit_group;" ::: "memory");
        }

        const uint32_t stCur = base + (kc % NSTAGE) * GSTAGE;
#pragma unroll
        for (int ks = 0; ks < 2; ks++) {
            const uint32_t ko = ks * 32;
            uint32_t bh[2][4];
#pragma unroll
            for (int p = 0; p < 2; p++)
                ldsm_x4(bh[p], stCur + GTILE + bOffB[p] + ko);
#pragma unroll
            for (int mi = 0; mi < 4; mi++) {
                uint32_t ah[4];
                ldsm_x4(ah, stCur + aOffB[mi] + ko);
#pragma unroll
                for (int ni = 0; ni < 4; ni++) {
                    const int p = ni >> 1, h = (ni & 1) * 2;
                    mma_f16(acc[mi][ni], ah, &bh[p][h]);
                }
            }
        }
    }

    // epilogue: branch tiles -> fp16 g_C1h; mlp tiles -> tanh fp32 g_C1m
    const bool isMlp = (nBase >= 512);
    const int rBase = tileM + warp_m * 64 + (lane >> 2);
    const int cBase = nBase + warp_n * 32 + 2 * (lane & 3);
#pragma unroll
    for (int mi = 0; mi < 4; mi++) {
#pragma unroll
        for (int half = 0; half < 2; half++) {
            const int row = rBase + mi * 16 + half * 8;
            if (row >= M) continue;
#pragma unroll
            for (int ni = 0; ni < 4; ni++) {
                const int col = cBase + ni * 8;
                float v0 = acc[mi][ni][half * 2 + 0];
                float v1 = acc[mi][ni][half * 2 + 1];
                if (isMlp) {
                    v0 = tanhf(v0 + mlp1_b[col - 512]);
                    v1 = tanhf(v1 + mlp1_b[col - 511]);
                    *reinterpret_cast<float2*>(g_C1m + (size_t)row * 256 + (col - 512)) =
                        make_float2(v0, v1);
                } else {
                    *reinterpret_cast<__half2*>(g_C1h + (size_t)row * 512 + col) =
                        __floats2half2_rn(v0, v1);
                }
            }
        }
    }
}

// ---------------- fused layer-1 aggregation: branch-parallel half2 gather ----------------
__global__ __launch_bounds__(256)
void gather_att(const float* __restrict__ b1r1,
                const float* __restrict__ b1r2,
                const float* __restrict__ af) {
    const int i = blockIdx.x;
    const int t = threadIdx.x;
    const int lane = t & 31, warp = t >> 5;
    const int br = t >> 7;                // 0: adj/v1, 1: s/v2
    const int u = (t & 127) * 2;          // first of 2 hidden units

    __shared__ float sv[768];             // v1[0..255], v2[256..511], v3[512..767]
    __shared__ float red[8][3];

    float s0 = 0.f, s1 = 0.f;
    {
        const int n = min(br ? g_cnt_s[i] : g_cnt_adj[i], ECAP);
        const float2* eb = (br ? g_edge_s : g_edge_adj) + (size_t)i * ECAP;
        const size_t colOff = (size_t)(br * 256 + u);
        for (int e = 0; e < n; e++) {
            float2 ev = __ldg(eb + e);
            int c = __float_as_int(ev.x);
            __half2 hv = __ldg(reinterpret_cast<const __half2*>(
                                   g_C1h + (size_t)c * 512 + colOff));
            float2 f = __half22float2(hv);
            s0 += ev.y * f.x;
            s1 += ev.y * f.y;
        }
        const float* bias = br ? b1r2 : b1r1;
        s0 += bias[u]; s1 += bias[u + 1];
    }
    float t0 = 0.f, t1 = 0.f;
    if (br == 0) {
        float2 v3p = *reinterpret_cast<const float2*>(g_C1m + (size_t)i * 256 + u);
        t0 = v3p.x; t1 = v3p.y;
        sv[512 + u] = t0; sv[513 + u] = t1;
    }
    sv[br * 256 + u] = s0;
    sv[br * 256 + u + 1] = s1;

    const int r0 = br * 256 + u;
    float p0 = s0 * af[r0 * 3 + 0] + s1 * af[(r0 + 1) * 3 + 0];
    float p1 = s0 * af[r0 * 3 + 1] + s1 * af[(r0 + 1) * 3 + 1];
    float p2 = s0 * af[r0 * 3 + 2] + s1 * af[(r0 + 1) * 3 + 2];
    if (br == 0) {
        const int r3 = 512 + u;
        p0 += t0 * af[r3 * 3 + 0] + t1 * af[(r3 + 1) * 3 + 0];
        p1 += t0 * af[r3 * 3 + 1] + t1 * af[(r3 + 1) * 3 + 1];
        p2 += t0 * af[r3 * 3 + 2] + t1 * af[(r3 + 1) * 3 + 2];
    }

#pragma unroll
    for (int off = 16; off; off >>= 1) {
        p0 += __shfl_xor_sync(0xffffffffu, p0, off);
        p1 += __shfl_xor_sync(0xffffffffu, p1, off);
        p2 += __shfl_xor_sync(0xffffffffu, p2, off);
    }
    if (lane == 0) { red[warp][0] = p0; red[warp][1] = p1; red[warp][2] = p2; }
    __syncthreads();

    float a0 = 0.f, a1 = 0.f, a2 = 0.f;
#pragma unroll
    for (int w = 0; w < 8; w++) { a0 += red[w][0]; a1 += red[w][1]; a2 += red[w][2]; }

    a0 = fabsf(a0); a1 = fabsf(a1); a2 = fabsf(a2);
    float m = fmaxf(a0, fmaxf(a1, a2));
    float e0 = __expf(a0 - m), e1 = __expf(a1 - m), e2 = __expf(a2 - m);
    float inv = 1.0f / (e0 + e1 + e2);
    float w0 = e0 * inv, w1 = e1 * inv, w2 = e2 * inv;

    g_X1[(size_t)i * 256 + t] = sv[t] * w0 + sv[256 + t] * w1 + sv[512 + t] * w2;
}

// ---------------- GEMM2 fused: Z2 (r1,r2 cols) + out init ----------------
__global__ void gemm2_out(const float* __restrict__ W2r1,
                          const float* __restrict__ W2r2,
                          const float* __restrict__ mlp2_W,
                          const float* __restrict__ b2r1,
                          const float* __restrict__ b2r2,
                          const float* __restrict__ mlp2_b,
                          float* __restrict__ out, int M) {
    __shared__ float Ws[256 * 6];
    for (int t = threadIdx.x; t < 256 * 6; t += blockDim.x) {
        int k = t / 6, j = t % 6;
        float v;
        if (j < 2)      v = W2r1[k * 2 + j];
        else if (j < 4) v = W2r2[k * 2 + (j - 2)];
        else            v = mlp2_W[k * 2 + (j - 4)];
        Ws[t] = v;
    }
    __syncthreads();

    int warp = threadIdx.x >> 5, lane = threadIdx.x & 31;
    int row = blockIdx.x * 8 + warp;
    if (row >= M) return;

    float acc[6] = {0.f, 0.f, 0.f, 0.f, 0.f, 0.f};
    const float* xr = g_X1 + (size_t)row * 256;
    for (int k = lane; k < 256; k += 32) {
        float xv = xr[k];
#pragma unroll
        for (int j = 0; j < 6; j++) acc[j] = fmaf(xv, Ws[k * 6 + j], acc[j]);
    }
#pragma unroll
    for (int off = 16; off; off >>= 1)
#pragma unroll
        for (int j = 0; j < 6; j++) acc[j] += __shfl_xor_sync(0xffffffffu, acc[j], off);

    if (lane == 0) {
        float* z = g_Z2 + (size_t)row * 4;
        z[0] = acc[0]; z[1] = acc[1]; z[2] = acc[2]; z[3] = acc[3];
        out[row * 2 + 0] = b2r1[0] + b2r2[0] + tanhf(acc[4] + mlp2_b[0]);
        out[row * 2 + 1] = b2r1[1] + b2r2[1] + tanhf(acc[5] + mlp2_b[1]);
    }
}

// ---------------- layer-2 aggregation: warp-per-node gather, no atomics ----------------
__global__ __launch_bounds__(256)
void gather2_out(float* __restrict__ out, int M) {
    const int warp = threadIdx.x >> 5, lane = threadIdx.x & 31;
    const int i = blockIdx.x * 8 + warp;
    if (i >= M) return;

    float s0 = 0.f, s1 = 0.f;
    {
        const int n = min(g_cnt_adj[i], ECAP);
        const float2* eb = g_edge_adj + (size_t)i * ECAP;
        for (int e = lane; e < n; e += 32) {
            float2 ev = __ldg(eb + e);
            int c = __float_as_int(ev.x);
            float2 z = *reinterpret_cast<const float2*>(g_Z2 + (size_t)c * 4);
            s0 += ev.y * z.x;
            s1 += ev.y * z.y;
        }
    }
    {
        const int n = min(g_cnt_s[i], ECAP);
        const float2* eb = g_edge_s + (size_t)i * ECAP;
        for (int e = lane; e < n; e += 32) {
            float2 ev = __ldg(eb + e);
            int c = __float_as_int(ev.x);
            float2 z = *reinterpret_cast<const float2*>(g_Z2 + (size_t)c * 4 + 2);
            s0 += ev.y * z.x;
            s1 += ev.y * z.y;
        }
    }
#pragma unroll
    for (int off = 16; off; off >>= 1) {
        s0 += __shfl_xor_sync(0xffffffffu, s0, off);
        s1 += __shfl_xor_sync(0xffffffffu, s1, off);
    }
    if (lane == 0) {
        out[i * 2 + 0] += s0;
        out[i * 2 + 1] += s1;
    }
}

// ---------------- launch ----------------
extern "C" void kernel_launch(void* const* d_in, const int* in_sizes, int n_in,
                              void* d_out, int out_size) {
    const float* x        = (const float*)d_in[0];
    const int*   adj_rows = (const int*)d_in[1];
    const int*   adj_cols = (const int*)d_in[2];
    const float* adj_vals = (const float*)d_in[3];
    const int*   s_rows   = (const int*)d_in[4];
    const int*   s_cols   = (const int*)d_in[5];
    const float* s_vals   = (const float*)d_in[6];
    const float* W1r1     = (const float*)d_in[7];
    const float* b1r1     = (const float*)d_in[8];
    const float* W1r2     = (const float*)d_in[9];
    const float* b1r2     = (const float*)d_in[10];
    const float* mlp1_W   = (const float*)d_in[11];
    const float* mlp1_b   = (const float*)d_in[12];
    const float* af1_w    = (const float*)d_in[13];
    const float* W2r1     = (const float*)d_in[14];
    const float* b2r1     = (const float*)d_in[15];
    const float* W2r2     = (const float*)d_in[16];
    const float* b2r2     = (const float*)d_in[17];
    const float* mlp2_W   = (const float*)d_in[18];
    const float* mlp2_b   = (const float*)d_in[19];
    float* out = (float*)d_out;

    const int E = in_sizes[1];
    const int M = N_NODES;

    cudaFuncSetAttribute(gemm1_mma, cudaFuncAttributeMaxDynamicSharedMemorySize, GSMEM);

    // prep
    split_x_zero<<<1184, 256>>>(x);
    pack_w1<<<(768 * 768 + 255) / 256, 256>>>(W1r1, W1r2, mlp1_W);
    build_buckets<<<(2 * E + 255) / 256, 256>>>(adj_rows, adj_cols, adj_vals,
                                                s_rows, s_cols, s_vals, E);

    // layer 1 big GEMM on tensor cores (HMMA fp16, single product)
    dim3 g1(6, (M + 127) / 128);
    gemm1_mma<<<g1, 256, GSMEM>>>(mlp1_b, M);

    // layer 1 aggregation + attention fusion
    gather_att<<<M, 256>>>(b1r1, b1r2, af1_w);

    // layer 2
    gemm2_out<<<(M + 7) / 8, 256>>>(W2r1, W2r2, mlp2_W, b2r1, b2r2, mlp2_b, out, M);
    gather2_out<<<(M + 7) / 8, 256>>>(out, M);
}